// round 13
// baseline (speedup 1.0000x reference)
#include <cuda_runtime.h>
#include <cuda_bf16.h>
#include <cstdint>
#include <cstddef>

#define BB   512
#define TT   128
#define DIN  128
#define DHID 256

// ---------------------------------------------------------------------------
// Scratch (device globals; no allocations allowed)
// ---------------------------------------------------------------------------
__device__ float g_xg  [(size_t)BB * TT * 4 * DHID];   // fp32 gate pre-activations
__device__ uint2 g_pk  [(size_t)BB * TT * DHID / 2];   // packed hi/lo activations
__device__ uint2 g_wpk [(size_t)4 * DHID * DHID / 2];  // packed weights (reused)
__device__ uint2 g_hTpk[(size_t)BB * DHID / 2];        // packed hT
__device__ float g_xgd0[(size_t)BB * 4 * DIN];         // dec0 xg (constant over t)

// ---------------------------------------------------------------------------
// Helpers
// ---------------------------------------------------------------------------
__device__ __forceinline__ float sigf(float x) { return 1.0f / (1.0f + __expf(-x)); }
__device__ __forceinline__ float tanhe(float x) {
    x = fminf(fmaxf(x, -15.0f), 15.0f);
    float e = __expf(-2.0f * x);
    return __fdividef(1.0f - e, 1.0f + e);
}
__device__ __forceinline__ uint32_t pack_bf16x2(float a, float b) {
    uint32_t r; asm("cvt.rn.bf16x2.f32 %0, %1, %2;" : "=r"(r) : "f"(b), "f"(a)); return r;
}
__device__ __forceinline__ void split_pack(float f0, float f1,
                                           uint32_t& hi2, uint32_t& lo2) {
    float h0 = __bfloat162float(__float2bfloat16(f0));
    float h1 = __bfloat162float(__float2bfloat16(f1));
    hi2 = pack_bf16x2(h0, h1);
    lo2 = pack_bf16x2(f0 - h0, f1 - h1);
}
__device__ __forceinline__ uint32_t smem_u32(const void* p) {
    uint32_t a;
    asm("{ .reg .u64 t; cvta.to.shared.u64 t, %1; cvt.u32.u64 %0, t; }" : "=r"(a) : "l"(p));
    return a;
}
__device__ __forceinline__ uint32_t cl_rank() {
    uint32_t r; asm("mov.u32 %0, %%cluster_ctarank;" : "=r"(r)); return r;
}
__device__ __forceinline__ uint32_t mapa_u32(uint32_t addr, uint32_t rank) {
    uint32_t r;
    asm("mapa.shared::cluster.u32 %0, %1, %2;" : "=r"(r) : "r"(addr), "r"(rank));
    return r;
}
#define CLUSTER_SYNC_() do { \
    asm volatile("barrier.cluster.arrive.aligned;" ::: "memory"); \
    asm volatile("barrier.cluster.wait.aligned;"   ::: "memory"); \
} while (0)

__device__ __forceinline__ void mb_init(uint32_t mb, uint32_t cnt) {
    asm volatile("mbarrier.init.shared.b64 [%0], %1;" :: "r"(mb), "r"(cnt) : "memory");
}
__device__ __forceinline__ void mb_arrive_tx(uint32_t mb, uint32_t tx) {
    asm volatile("mbarrier.arrive.expect_tx.shared.b64 _, [%0], %1;"
                 :: "r"(mb), "r"(tx) : "memory");
}
__device__ __forceinline__ void mb_wait(uint32_t mb, uint32_t parity) {
    asm volatile(
        "{\n\t.reg .pred P;\n\t"
        "WL_%=:\n\t"
        "mbarrier.try_wait.parity.acquire.cluster.shared::cta.b64 P, [%0], %1, 0x989680;\n\t"
        "@P bra.uni WD_%=;\n\t"
        "bra.uni WL_%=;\n\t"
        "WD_%=:\n\t}"
        :: "r"(mb), "r"(parity) : "memory");
}
// 16-byte async store to (possibly remote) CTA smem + mbarrier tx signal
__device__ __forceinline__ void st_async_v4(uint32_t raddr, uint32_t rmbar,
                                            uint32_t a, uint32_t b,
                                            uint32_t c, uint32_t d) {
    asm volatile(
        "st.async.shared::cluster.mbarrier::complete_tx::bytes.v4.b32 "
        "[%0], {%2,%3,%4,%5}, [%1];"
        :: "r"(raddr), "r"(rmbar), "r"(a), "r"(b), "r"(c), "r"(d) : "memory");
}

__device__ __forceinline__ void mma_bf16(float4& c, const uint32_t a[4],
                                         uint32_t b0, uint32_t b1) {
    asm volatile(
        "mma.sync.aligned.m16n8k16.row.col.f32.bf16.bf16.f32 "
        "{%0,%1,%2,%3}, {%4,%5,%6,%7}, {%8,%9}, {%0,%1,%2,%3};"
        : "+f"(c.x), "+f"(c.y), "+f"(c.z), "+f"(c.w)
        : "r"(a[0]), "r"(a[1]), "r"(a[2]), "r"(a[3]), "r"(b0), "r"(b1));
}

// ---------------------------------------------------------------------------
// Recurrent LSTM body (R8 structure): bf16 hi/lo tensor cores, two-half
// pipeline, st.async + mbarrier-tx h exchange. R12 change: each P2 item owns
// FOUR consecutive hidden units (2 adjacent uint2 pairs = 16 contiguous B in
// hl), broadcast with one st.async.v4.b32 per peer -> arrivals per mbarrier
// phase halved, store instructions halved. Bytes per phase (TXB) unchanged.
// Timestep = 2 brackets: [P2(A,t);P1(B,t);bar][P2(B,t);P1(A,t+1);bar].
// ---------------------------------------------------------------------------
template <int H, int CL, int KH, int MPW>
__device__ __forceinline__ void lstm_body(
    const float* __restrict__ Whh, const float* __restrict__ xg,
    size_t xg_bs, int xg_ts,
    uint2* __restrict__ out_seq, uint2* __restrict__ out_final)
{
    constexpr int K    = H;
    constexpr int JC   = H / CL;
    constexpr int GR   = 4 * H / CL;
    constexpr int KT   = (K / 16) / KH;
    constexpr int MG   = (GR / 16) / MPW;
    static_assert(MG * KH == 16, "16 warps");
    constexpr int Bt   = 4 * CL;
    constexpr int HB   = Bt / 2;            // half-batch
    constexpr int NT   = HB / 8;            // n8 tiles per half
    static_assert(NT >= 1, "NT");
    constexpr int HLS2 = K / 2 + 4;         // uint2 stride per b row
    static_assert(HLS2 % 16 == 4, "banks");
    constexpr int SG   = HB + 2;
    constexpr int HSLOT = HB * HLS2;        // uint2 per (half,slot)
    constexpr int GSM_H = KH * GR * SG;
    constexpr uint32_t TXB = (uint32_t)HB * (K / 2) * 8;  // bytes per mbar phase
    constexpr int HL_OFF = 32;              // mbar block at smem start

    extern __shared__ char smraw[];
    uint2* hl  = reinterpret_cast<uint2*>(smraw + HL_OFF);            // [4][HB][HLS2]
    float* gsm = reinterpret_cast<float*>(smraw + HL_OFF + (size_t)4 * HSLOT * 8);

    const int tid = threadIdx.x, wid = tid >> 5, lane = tid & 31;
    const int gid = lane >> 2, tk = lane & 3;
    const uint32_t r = cl_rank();
    const int b0 = (blockIdx.x / CL) * Bt;
    const uint32_t sbase = smem_u32(smraw);

    const int mg = wid / KH, kh = wid % KH;

    // ---- preload Whh fragments -------------------------------------------
    uint32_t Ahi[MPW][KT][4], Alo[MPW][KT][4];
    #pragma unroll
    for (int mp = 0; mp < MPW; ++mp) {
        int m0 = (mg * MPW + mp) * 16;
        int j1 = m0 + gid, j2 = j1 + 8;
        const float* w1 = Whh + (size_t)((j1 / JC) * H + r * JC + (j1 % JC)) * K;
        const float* w2 = Whh + (size_t)((j2 / JC) * H + r * JC + (j2 % JC)) * K;
        #pragma unroll
        for (int kt = 0; kt < KT; ++kt) {
            int ka = (kh * KT + kt) * 16 + 2 * tk;
            split_pack(w1[ka],     w1[ka + 1], Ahi[mp][kt][0], Alo[mp][kt][0]);
            split_pack(w2[ka],     w2[ka + 1], Ahi[mp][kt][1], Alo[mp][kt][1]);
            split_pack(w1[ka + 8], w1[ka + 9], Ahi[mp][kt][2], Alo[mp][kt][2]);
            split_pack(w2[ka + 8], w2[ka + 9], Ahi[mp][kt][3], Alo[mp][kt][3]);
        }
    }
    // ---- init mbarriers + arm phase 0, zero h slots ------------------------
    if (tid == 0) {
        #pragma unroll
        for (int i = 0; i < 4; ++i) {
            mb_init(sbase + i * 8, 1);
            mb_arrive_tx(sbase + i * 8, TXB);
        }
    }
    for (int i = tid; i < 4 * HSLOT * 2; i += 512)
        reinterpret_cast<uint32_t*>(hl)[i] = 0u;
    __syncthreads();
    CLUSTER_SYNC_();          // all mbarriers live before any st.async

    // peer smem bases
    uint32_t pbase[CL];
    #pragma unroll
    for (int p = 0; p < CL; ++p) pbase[p] = mapa_u32(sbase, (uint32_t)p);

    // ---- phase-2 identity: each item owns 4 consecutive hidden units -------
    constexpr int IPB = JC / 4;             // items per batch row
    constexpr int ITh = HB * IPB;
    static_assert(ITh <= 256, "P2 items fit half the threads");
    const bool isB = tid >= 256;
    const int  lt  = isB ? tid - 256 : tid;
    const bool act = lt < ITh;
    const int  pbl = lt / IPB;
    const int  kl  = lt % IPB;
    const int  k0  = r * JC + 4 * kl;       // 4 hidden units k0..k0+3
    const int  kpg0 = (r * JC) / 2 + 2 * kl; // first uint2 pair (even)
    const int  gb  = b0 + (isB ? HB : 0) + pbl;
    float cv[4] = {0.f, 0.f, 0.f, 0.f};
    uint32_t phbits = 0;     // per-mbar phase parity
    float4 xr[4];
    if (act) {
        const float* xgt = xg + (size_t)gb * xg_bs;   // t = 0
        #pragma unroll
        for (int g = 0; g < 4; ++g)
            xr[g] = __ldg(reinterpret_cast<const float4*>(xgt + g * H + k0));
    }

    // ---- P1: bf16 MMAs for one (half, slot) --------------------------------
    auto P1 = [&](int halfidx, int slot, float* gso, bool dowait) {
        const int idx = halfidx * 2 + slot;
        if (dowait) {
            uint32_t mb = sbase + idx * 8;
            mb_wait(mb, (phbits >> idx) & 1u);
            phbits ^= (1u << idx);
            if (tid == 0) mb_arrive_tx(mb, TXB);   // re-arm next phase
        }
        const uint2* hb = hl + (size_t)idx * HSLOT;
        float4 C[MPW][NT];
        #pragma unroll
        for (int mp = 0; mp < MPW; ++mp)
            #pragma unroll
            for (int nt = 0; nt < NT; ++nt) C[mp][nt] = make_float4(0.f, 0.f, 0.f, 0.f);
        #pragma unroll
        for (int kt = 0; kt < KT; ++kt) {
            int kp0 = (kh * KT + kt) * 8 + tk;
            #pragma unroll
            for (int nt = 0; nt < NT; ++nt) {
                int n = nt * 8 + gid;
                uint2 u0 = hb[n * HLS2 + kp0];
                uint2 u1 = hb[n * HLS2 + kp0 + 4];
                #pragma unroll
                for (int mp = 0; mp < MPW; ++mp) {
                    mma_bf16(C[mp][nt], Ahi[mp][kt], u0.x, u1.x);
                    mma_bf16(C[mp][nt], Ahi[mp][kt], u0.y, u1.y);
                    mma_bf16(C[mp][nt], Alo[mp][kt], u0.x, u1.x);
                }
            }
        }
        float* gout = gso + kh * (GR * SG);
        #pragma unroll
        for (int mp = 0; mp < MPW; ++mp) {
            int m0 = (mg * MPW + mp) * 16;
            #pragma unroll
            for (int nt = 0; nt < NT; ++nt) {
                int col = nt * 8 + 2 * tk;
                *reinterpret_cast<float2*>(&gout[(m0 + gid) * SG + col]) =
                    make_float2(C[mp][nt].x, C[mp][nt].y);
                *reinterpret_cast<float2*>(&gout[(m0 + gid + 8) * SG + col]) =
                    make_float2(C[mp][nt].z, C[mp][nt].w);
            }
        }
    };

    // ---- P2: 4 gates/cells per item + one v4 broadcast per peer ------------
    auto P2 = [&](int t, int halfidx) {
        const float* gp0 = gsm + halfidx * GSM_H;
        float s[4][4];
        #pragma unroll
        for (int g = 0; g < 4; ++g) {
            float4 a = xr[g];
            float sv0 = a.x, sv1 = a.y, sv2 = a.z, sv3 = a.w;
            int row = (g * JC + 4 * kl) * SG + pbl;
            #pragma unroll
            for (int khx = 0; khx < KH; ++khx) {
                const float* gp = gp0 + khx * (GR * SG);
                sv0 += gp[row];
                sv1 += gp[row + SG];
                sv2 += gp[row + 2 * SG];
                sv3 += gp[row + 3 * SG];
            }
            s[g][0] = sv0; s[g][1] = sv1; s[g][2] = sv2; s[g][3] = sv3;
        }
        float hv[4];
        #pragma unroll
        for (int j = 0; j < 4; ++j) {
            float i_ = sigf(s[0][j]);
            float f_ = sigf(s[1][j]);
            float g_ = tanhe(s[2][j]);
            float o_ = sigf(s[3][j]);
            cv[j] = f_ * cv[j] + i_ * g_;
            hv[j] = o_ * tanhe(cv[j]);
        }

        uint32_t hiA, loA, hiB, loB;
        split_pack(hv[0], hv[1], hiA, loA);
        split_pack(hv[2], hv[3], hiB, loB);

        if (t + 1 < TT) {   // broadcast (skipped on last step)
            const int idx = halfidx * 2 + ((t + 1) & 1);
            uint32_t off_mb  = (uint32_t)idx * 8;
            uint32_t off_dat = HL_OFF +
                (uint32_t)(((idx * HB + pbl) * HLS2 + kpg0) * 8);   // 16B aligned
            #pragma unroll
            for (int p = 0; p < CL; ++p)
                st_async_v4(pbase[p] + off_dat, pbase[p] + off_mb,
                            hiA, loA, hiB, loB);
        }

        if (out_seq)
            *reinterpret_cast<uint4*>(
                &out_seq[((size_t)gb * TT + t) * (H / 2) + kpg0]) =
                make_uint4(hiA, loA, hiB, loB);
        if (out_final && t == TT - 1)
            *reinterpret_cast<uint4*>(
                &out_final[(size_t)gb * (H / 2) + kpg0]) =
                make_uint4(hiA, loA, hiB, loB);

        // prefetch xg for t+1 (skip when constant over t, or on last step)
        if (xg_ts != 0 && t + 1 < TT) {
            const float* xgt = xg + (size_t)(t + 1) * xg_ts + (size_t)gb * xg_bs;
            #pragma unroll
            for (int g = 0; g < 4; ++g)
                xr[g] = __ldg(reinterpret_cast<const float4*>(xgt + g * H + k0));
        }
    };

    // ---- prologue + main loop ----------------------------------------------
    P1(0, 0, gsm, false);          // h(0)=0, slot prefilled
    __syncthreads();

    for (int t = 0; t < TT; ++t) {
        // even bracket: P2(A,t) || P1(B, t&1)
        if (!isB && act) P2(t, 0);
        P1(1, t & 1, gsm + GSM_H, t > 0);
        __syncthreads();
        // odd bracket: P2(B,t) || P1(A, (t+1)&1)
        if (isB && act) P2(t, 1);
        if (t + 1 < TT) P1(0, (t + 1) & 1, gsm, true);
        __syncthreads();
    }
    CLUSTER_SYNC_();   // keep peer smem alive until everyone is done
}

// enc: H=256, CL=8, KH=4, MPW=2   dec: H=128, CL=4, KH=2, MPW=1  (R8 config)
__global__ void __cluster_dims__(8, 1, 1) __launch_bounds__(512, 1)
lstm_enc(const float* __restrict__ Whh, const float* __restrict__ xg,
         size_t xg_bs, int xg_ts, uint2* __restrict__ out_seq,
         uint2* __restrict__ out_final)
{
    lstm_body<DHID, 8, 4, 2>(Whh, xg, xg_bs, xg_ts, out_seq, out_final);
}
__global__ void __cluster_dims__(4, 1, 1) __launch_bounds__(512, 1)
lstm_dec(const float* __restrict__ Whh, const float* __restrict__ xg,
         size_t xg_bs, int xg_ts, uint2* __restrict__ out_seq,
         uint2* __restrict__ out_final)
{
    lstm_body<DIN, 4, 2, 1>(Whh, xg, xg_bs, xg_ts, out_seq, out_final);
}

// ---------------------------------------------------------------------------
// Elementwise pack: fp32 pairs -> {bf16 hi x2, bf16 lo x2}
// ---------------------------------------------------------------------------
__global__ __launch_bounds__(256) void pack_hilo_kernel(
    const float* __restrict__ src, uint2* __restrict__ dst, int npairs)
{
    int i = blockIdx.x * 256 + threadIdx.x;
    if (i >= npairs) return;
    float2 f = reinterpret_cast<const float2*>(src)[i];
    uint32_t h2, l2;
    split_pack(f.x, f.y, h2, l2);
    dst[i] = make_uint2(h2, l2);
}

// ---------------------------------------------------------------------------
// Tensor-core GEMM, pre-packed bf16 hi/lo operands (proven R7/R8)
// ---------------------------------------------------------------------------
__global__ __launch_bounds__(256, 2) void hgemm_pk(
    const uint2* __restrict__ Apk, const uint2* __restrict__ Bpk,
    const float* __restrict__ b1, const float* __restrict__ b2,
    float* __restrict__ C, int M, int N, int Kp)
{
    __shared__ uint2 As[128][18];
    __shared__ uint2 Bs[64][18];

    const int tid = threadIdx.x, wid = tid >> 5, lane = tid & 31;
    const int gid = lane >> 2, tk = lane & 3;
    const int bm = blockIdx.y * 128;
    const int bn = blockIdx.x * 64;
    const int wm = (wid & 3) * 32;
    const int wn = (wid >> 2) * 32;

    float4 Cc[2][4];
    #pragma unroll
    for (int mp = 0; mp < 2; ++mp)
        #pragma unroll
        for (int nt = 0; nt < 4; ++nt) Cc[mp][nt] = make_float4(0.f, 0.f, 0.f, 0.f);

    const int arow = tid >> 1, ac = (tid & 1) * 8;
    const int brow = tid >> 2, bc = (tid & 3) * 4;
    const uint2* Ap = Apk + (size_t)(bm + arow) * Kp + ac;
    const uint2* Bp = Bpk + (size_t)(bn + brow) * Kp + bc;

    for (int kb = 0; kb < Kp; kb += 16) {
        #pragma unroll
        for (int v = 0; v < 4; ++v) {
            uint4 w = *reinterpret_cast<const uint4*>(Ap + kb + 2 * v);
            As[arow][ac + 2 * v]     = make_uint2(w.x, w.y);
            As[arow][ac + 2 * v + 1] = make_uint2(w.z, w.w);
        }
        #pragma unroll
        for (int v = 0; v < 2; ++v) {
            uint4 w = *reinterpret_cast<const uint4*>(Bp + kb + 2 * v);
            Bs[brow][bc + 2 * v]     = make_uint2(w.x, w.y);
            Bs[brow][bc + 2 * v + 1] = make_uint2(w.z, w.w);
        }
        __syncthreads();

        #pragma unroll
        for (int kt = 0; kt < 2; ++kt) {
            int kp = kt * 8 + tk;
            uint32_t Ah[2][4], Al[2][4];
            #pragma unroll
            for (int mp = 0; mp < 2; ++mp) {
                int r1 = wm + mp * 16 + gid;
                uint2 u00 = As[r1][kp],     u01 = As[r1][kp + 4];
                uint2 u10 = As[r1 + 8][kp], u11 = As[r1 + 8][kp + 4];
                Ah[mp][0] = u00.x; Ah[mp][1] = u10.x; Ah[mp][2] = u01.x; Ah[mp][3] = u11.x;
                Al[mp][0] = u00.y; Al[mp][1] = u10.y; Al[mp][2] = u01.y; Al[mp][3] = u11.y;
            }
            #pragma unroll
            for (int nt = 0; nt < 4; ++nt) {
                int n = wn + nt * 8 + gid;
                uint2 u0 = Bs[n][kp];
                uint2 u1 = Bs[n][kp + 4];
                #pragma unroll
                for (int mp = 0; mp < 2; ++mp) {
                    mma_bf16(Cc[mp][nt], Ah[mp], u0.x, u1.x);
                    mma_bf16(Cc[mp][nt], Ah[mp], u0.y, u1.y);
                    mma_bf16(Cc[mp][nt], Al[mp], u0.x, u1.x);
                }
            }
        }
        __syncthreads();
    }

    #pragma unroll
    for (int nt = 0; nt < 4; ++nt) {
        int n = bn + wn + nt * 8 + 2 * tk;
        float bb0 = b1[n]     + (b2 ? b2[n]     : 0.0f);
        float bb1 = b1[n + 1] + (b2 ? b2[n + 1] : 0.0f);
        #pragma unroll
        for (int mp = 0; mp < 2; ++mp) {
            int m1 = bm + wm + mp * 16 + gid;
            *reinterpret_cast<float2*>(C + (size_t)m1 * N + n) =
                make_float2(Cc[mp][nt].x + bb0, Cc[mp][nt].y + bb1);
            *reinterpret_cast<float2*>(C + (size_t)(m1 + 8) * N + n) =
                make_float2(Cc[mp][nt].z + bb0, Cc[mp][nt].w + bb1);
        }
    }
}

// ---------------------------------------------------------------------------
// Launch
// ---------------------------------------------------------------------------
// enc: 32 + 4*(16*132)*8 + 2*(4*128*18)*4 = 32+67584+73728 = 141344
static const int SMEM_ENC = 141344;
// dec: 32 + 4*(8*68)*8 + 2*(2*128*10)*4  = 32+17408+20480 =  37920
static const int SMEM_DEC = 37920;

static inline int cdiv(int a, int b) { return (a + b - 1) / b; }

extern "C" void kernel_launch(void* const* d_in, const int* in_sizes, int n_in,
                              void* d_out, int out_size)
{
    (void)in_sizes; (void)n_in; (void)out_size;
    const float* x        = (const float*)d_in[0];
    const float* e0_Wih   = (const float*)d_in[1];
    const float* e0_Whh   = (const float*)d_in[2];
    const float* e0_bih   = (const float*)d_in[3];
    const float* e0_bhh   = (const float*)d_in[4];
    const float* e1_Wih   = (const float*)d_in[5];
    const float* e1_Whh   = (const float*)d_in[6];
    const float* e1_bih   = (const float*)d_in[7];
    const float* e1_bhh   = (const float*)d_in[8];
    const float* d0_Wih   = (const float*)d_in[9];
    const float* d0_Whh   = (const float*)d_in[10];
    const float* d0_bih   = (const float*)d_in[11];
    const float* d0_bhh   = (const float*)d_in[12];
    const float* d1_Wih   = (const float*)d_in[13];
    const float* d1_Whh   = (const float*)d_in[14];
    const float* d1_bih   = (const float*)d_in[15];
    const float* d1_bhh   = (const float*)d_in[16];
    const float* out_W    = (const float*)d_in[17];
    const float* out_b    = (const float*)d_in[18];
    float* out = (float*)d_out;

    float *xg, *xgd0;
    uint2 *pk, *wpk, *hTpk;
    cudaGetSymbolAddress((void**)&xg,   g_xg);
    cudaGetSymbolAddress((void**)&pk,   g_pk);
    cudaGetSymbolAddress((void**)&wpk,  g_wpk);
    cudaGetSymbolAddress((void**)&hTpk, g_hTpk);
    cudaGetSymbolAddress((void**)&xgd0, g_xgd0);

    cudaFuncSetAttribute(lstm_enc,
                         cudaFuncAttributeMaxDynamicSharedMemorySize, SMEM_ENC);
    cudaFuncSetAttribute(lstm_dec,
                         cudaFuncAttributeMaxDynamicSharedMemorySize, SMEM_DEC);

    const int MT = BB * TT;  // 65536

    // 1) pack x, pack e0_Wih ; xg0 = x @ e0_Wih^T + b
    {
        int np = MT * DIN / 2;
        pack_hilo_kernel<<<cdiv(np, 256), 256>>>(x, pk, np);
        int nw = 4 * DHID * DIN / 2;
        pack_hilo_kernel<<<cdiv(nw, 256), 256>>>(e0_Wih, wpk, nw);
        hgemm_pk<<<dim3(4 * DHID / 64, MT / 128), 256>>>(
            pk, wpk, e0_bih, e0_bhh, xg, MT, 4 * DHID, DIN / 2);
    }
    // 2) enc0 recurrence -> e0 packed
    lstm_enc<<<128, 512, SMEM_ENC>>>(
        e0_Whh, xg, (size_t)TT * 4 * DHID, 4 * DHID, pk, nullptr);

    // 3) pack e1_Wih ; xg1 = e0 @ e1_Wih^T + b
    {
        int nw = 4 * DHID * DHID / 2;
        pack_hilo_kernel<<<cdiv(nw, 256), 256>>>(e1_Wih, wpk, nw);
        hgemm_pk<<<dim3(4 * DHID / 64, MT / 128), 256>>>(
            pk, wpk, e1_bih, e1_bhh, xg, MT, 4 * DHID, DHID / 2);
    }
    // 4) enc1 recurrence -> hT packed
    lstm_enc<<<128, 512, SMEM_ENC>>>(
        e1_Whh, xg, (size_t)TT * 4 * DHID, 4 * DHID, nullptr, hTpk);

    // 5) pack d0_Wih ; xgd0 = hT @ d0_Wih^T + b
    {
        int nw = 4 * DIN * DHID / 2;
        pack_hilo_kernel<<<cdiv(nw, 256), 256>>>(d0_Wih, wpk, nw);
        hgemm_pk<<<dim3(4 * DIN / 64, BB / 128), 256>>>(
            hTpk, wpk, d0_bih, d0_bhh, xgd0, BB, 4 * DIN, DHID / 2);
    }
    // 6) dec0 recurrence (t-stride 0) -> d0 packed
    lstm_dec<<<128, 512, SMEM_DEC>>>(
        d0_Whh, xgd0, (size_t)4 * DIN, 0, pk, nullptr);

    // 7) pack d1_Wih ; xgd1 = d0 @ d1_Wih^T + b
    {
        int nw = 4 * DIN * DIN / 2;
        pack_hilo_kernel<<<cdiv(nw, 256), 256>>>(d1_Wih, wpk, nw);
        hgemm_pk<<<dim3(4 * DIN / 64, MT / 128), 256>>>(
            pk, wpk, d1_bih, d1_bhh, xg, MT, 4 * DIN, DIN / 2);
    }
    // 8) dec1 recurrence -> d1 packed
    lstm_dec<<<128, 512, SMEM_DEC>>>(
        d1_Whh, xg, (size_t)TT * 4 * DIN, 4 * DIN, pk, nullptr);

    // 9) pack out_W ; out = d1 @ out_W^T + out_b
    {
        int nw = DIN * DIN / 2;
        pack_hilo_kernel<<<cdiv(nw, 256), 256>>>(out_W, wpk, nw);
        hgemm_pk<<<dim3(DIN / 64, MT / 128), 256>>>(
            pk, wpk, out_b, nullptr, out, MT, DIN, DIN / 2);
    }
}

// round 14
// speedup vs baseline: 1.2447x; 1.2447x over previous
#include <cuda_runtime.h>
#include <cuda_bf16.h>
#include <cstdint>
#include <cstddef>

#define BB   512
#define TT   128
#define DIN  128
#define DHID 256

// ---------------------------------------------------------------------------
// Scratch (device globals; no allocations allowed)
// ---------------------------------------------------------------------------
__device__ float g_xg  [(size_t)BB * TT * 4 * DHID];   // fp32 gate pre-activations
__device__ uint2 g_pk  [(size_t)BB * TT * DHID / 2];   // packed hi/lo activations
__device__ uint2 g_wpk [(size_t)4 * DHID * DHID / 2];  // packed weights (reused)
__device__ uint2 g_hTpk[(size_t)BB * DHID / 2];        // packed hT
__device__ float g_xgd0[(size_t)BB * 4 * DIN];         // dec0 xg (constant over t)

// ---------------------------------------------------------------------------
// Helpers
// ---------------------------------------------------------------------------
__device__ __forceinline__ float sigf(float x) { return 1.0f / (1.0f + __expf(-x)); }
__device__ __forceinline__ float tanhe(float x) {
    x = fminf(fmaxf(x, -15.0f), 15.0f);
    float e = __expf(-2.0f * x);
    return __fdividef(1.0f - e, 1.0f + e);
}
__device__ __forceinline__ uint32_t pack_bf16x2(float a, float b) {
    uint32_t r; asm("cvt.rn.bf16x2.f32 %0, %1, %2;" : "=r"(r) : "f"(b), "f"(a)); return r;
}
__device__ __forceinline__ void split_pack(float f0, float f1,
                                           uint32_t& hi2, uint32_t& lo2) {
    float h0 = __bfloat162float(__float2bfloat16(f0));
    float h1 = __bfloat162float(__float2bfloat16(f1));
    hi2 = pack_bf16x2(h0, h1);
    lo2 = pack_bf16x2(f0 - h0, f1 - h1);
}
__device__ __forceinline__ uint32_t smem_u32(const void* p) {
    uint32_t a;
    asm("{ .reg .u64 t; cvta.to.shared.u64 t, %1; cvt.u32.u64 %0, t; }" : "=r"(a) : "l"(p));
    return a;
}
__device__ __forceinline__ uint32_t cl_rank() {
    uint32_t r; asm("mov.u32 %0, %%cluster_ctarank;" : "=r"(r)); return r;
}
__device__ __forceinline__ uint32_t mapa_u32(uint32_t addr, uint32_t rank) {
    uint32_t r;
    asm("mapa.shared::cluster.u32 %0, %1, %2;" : "=r"(r) : "r"(addr), "r"(rank));
    return r;
}
#define CLUSTER_SYNC_() do { \
    asm volatile("barrier.cluster.arrive.aligned;" ::: "memory"); \
    asm volatile("barrier.cluster.wait.aligned;"   ::: "memory"); \
} while (0)

__device__ __forceinline__ void mb_init(uint32_t mb, uint32_t cnt) {
    asm volatile("mbarrier.init.shared.b64 [%0], %1;" :: "r"(mb), "r"(cnt) : "memory");
}
__device__ __forceinline__ void mb_arrive_tx(uint32_t mb, uint32_t tx) {
    asm volatile("mbarrier.arrive.expect_tx.shared.b64 _, [%0], %1;"
                 :: "r"(mb), "r"(tx) : "memory");
}
__device__ __forceinline__ void mb_wait(uint32_t mb, uint32_t parity) {
    asm volatile(
        "{\n\t.reg .pred P;\n\t"
        "WL_%=:\n\t"
        "mbarrier.try_wait.parity.acquire.cluster.shared::cta.b64 P, [%0], %1, 0x989680;\n\t"
        "@P bra.uni WD_%=;\n\t"
        "bra.uni WL_%=;\n\t"
        "WD_%=:\n\t}"
        :: "r"(mb), "r"(parity) : "memory");
}
// async store to (possibly remote) CTA smem, signaling its mbarrier tx count
__device__ __forceinline__ void st_async_v2(uint32_t raddr, uint32_t rmbar,
                                            uint32_t a, uint32_t b) {
    asm volatile(
        "st.async.shared::cluster.mbarrier::complete_tx::bytes.v2.b32 [%0], {%2,%3}, [%1];"
        :: "r"(raddr), "r"(rmbar), "r"(a), "r"(b) : "memory");
}

__device__ __forceinline__ void mma_bf16(float4& c, const uint32_t a[4],
                                         uint32_t b0, uint32_t b1) {
    asm volatile(
        "mma.sync.aligned.m16n8k16.row.col.f32.bf16.bf16.f32 "
        "{%0,%1,%2,%3}, {%4,%5,%6,%7}, {%8,%9}, {%0,%1,%2,%3};"
        : "+f"(c.x), "+f"(c.y), "+f"(c.z), "+f"(c.w)
        : "r"(a[0]), "r"(a[1]), "r"(a[2]), "r"(a[3]), "r"(b0), "r"(b1));
}

// ---------------------------------------------------------------------------
// Recurrent LSTM body — EXACT R8 shape (3348us best): bf16 hi/lo tensor
// cores, two-half pipeline, st.async + mbarrier-tx h exchange.
// CL CTAs per cluster share one batch-tile of Bt=4*CL rows; rank r owns gate
// rows {g*H + r*JC + cl}. Whh in registers (bf16 hi + residual lo).
// h exchanged as packed uint2 {hi bf16x2, lo bf16x2} per k-pair via st.async;
// consumer CTA waits on its own mbarrier reaching HB*(K/2)*8 bytes.
// Timestep = 2 brackets: [P2(A,t);P1(B,t);bar][P2(B,t);P1(A,t+1);bar].
// ---------------------------------------------------------------------------
template <int H, int CL, int KH, int MPW>
__device__ __forceinline__ void lstm_body(
    const float* __restrict__ Whh, const float* __restrict__ xg,
    size_t xg_bs, int xg_ts,
    uint2* __restrict__ out_seq, uint2* __restrict__ out_final)
{
    constexpr int K    = H;
    constexpr int JC   = H / CL;
    constexpr int GR   = 4 * H / CL;
    constexpr int KT   = (K / 16) / KH;
    constexpr int MG   = (GR / 16) / MPW;
    static_assert(MG * KH == 16, "16 warps");
    constexpr int Bt   = 4 * CL;
    constexpr int HB   = Bt / 2;            // half-batch
    constexpr int NT   = HB / 8;            // n8 tiles per half
    static_assert(NT >= 1, "NT");
    constexpr int HLS2 = K / 2 + 4;         // uint2 stride per b row
    static_assert(HLS2 % 16 == 4, "banks");
    constexpr int SG   = HB + 2;
    constexpr int HSLOT = HB * HLS2;        // uint2 per (half,slot)
    constexpr int GSM_H = KH * GR * SG;
    constexpr uint32_t TXB = (uint32_t)HB * (K / 2) * 8;  // bytes per mbar phase
    constexpr int HL_OFF = 32;              // mbar block at smem start

    extern __shared__ char smraw[];
    uint2* hl  = reinterpret_cast<uint2*>(smraw + HL_OFF);            // [4][HB][HLS2]
    float* gsm = reinterpret_cast<float*>(smraw + HL_OFF + (size_t)4 * HSLOT * 8);

    const int tid = threadIdx.x, wid = tid >> 5, lane = tid & 31;
    const int gid = lane >> 2, tk = lane & 3;
    const uint32_t r = cl_rank();
    const int b0 = (blockIdx.x / CL) * Bt;
    const uint32_t sbase = smem_u32(smraw);

    const int mg = wid / KH, kh = wid % KH;

    // ---- preload Whh fragments -------------------------------------------
    uint32_t Ahi[MPW][KT][4], Alo[MPW][KT][4];
    #pragma unroll
    for (int mp = 0; mp < MPW; ++mp) {
        int m0 = (mg * MPW + mp) * 16;
        int j1 = m0 + gid, j2 = j1 + 8;
        const float* w1 = Whh + (size_t)((j1 / JC) * H + r * JC + (j1 % JC)) * K;
        const float* w2 = Whh + (size_t)((j2 / JC) * H + r * JC + (j2 % JC)) * K;
        #pragma unroll
        for (int kt = 0; kt < KT; ++kt) {
            int ka = (kh * KT + kt) * 16 + 2 * tk;
            split_pack(w1[ka],     w1[ka + 1], Ahi[mp][kt][0], Alo[mp][kt][0]);
            split_pack(w2[ka],     w2[ka + 1], Ahi[mp][kt][1], Alo[mp][kt][1]);
            split_pack(w1[ka + 8], w1[ka + 9], Ahi[mp][kt][2], Alo[mp][kt][2]);
            split_pack(w2[ka + 8], w2[ka + 9], Ahi[mp][kt][3], Alo[mp][kt][3]);
        }
    }
    // ---- init mbarriers + arm phase 0, zero h slots ------------------------
    if (tid == 0) {
        #pragma unroll
        for (int i = 0; i < 4; ++i) {
            mb_init(sbase + i * 8, 1);
            mb_arrive_tx(sbase + i * 8, TXB);
        }
    }
    for (int i = tid; i < 4 * HSLOT * 2; i += 512)
        reinterpret_cast<uint32_t*>(hl)[i] = 0u;
    __syncthreads();
    CLUSTER_SYNC_();          // all mbarriers live before any st.async

    // peer smem bases
    uint32_t pbase[CL];
    #pragma unroll
    for (int p = 0; p < CL; ++p) pbase[p] = mapa_u32(sbase, (uint32_t)p);

    // ---- phase-2 identity ---------------------------------------------------
    constexpr int ITh = HB * (JC / 2);
    static_assert(ITh <= 256, "P2 items fit half the threads");
    const bool isB = tid >= 256;
    const int  lt  = isB ? tid - 256 : tid;
    const bool act = lt < ITh;
    const int  pbl = lt / (JC / 2);
    const int  kl  = lt % (JC / 2);
    const int  k0  = r * JC + 2 * kl;
    const int  kpg = (r * JC) / 2 + kl;
    const int  gb  = b0 + (isB ? HB : 0) + pbl;
    float cv0 = 0.0f, cv1 = 0.0f;
    uint32_t phbits = 0;     // per-mbar phase parity
    float2 xr[4];
    if (act) {
        const float* xgt = xg + (size_t)gb * xg_bs;   // t = 0
        #pragma unroll
        for (int g = 0; g < 4; ++g)
            xr[g] = *reinterpret_cast<const float2*>(xgt + g * H + k0);
    }

    // ---- P1: bf16 MMAs for one (half, slot) --------------------------------
    auto P1 = [&](int halfidx, int slot, float* gso, bool dowait) {
        const int idx = halfidx * 2 + slot;
        if (dowait) {
            uint32_t mb = sbase + idx * 8;
            mb_wait(mb, (phbits >> idx) & 1u);
            phbits ^= (1u << idx);
            if (tid == 0) mb_arrive_tx(mb, TXB);   // re-arm next phase
        }
        const uint2* hb = hl + (size_t)idx * HSLOT;
        float4 C[MPW][NT];
        #pragma unroll
        for (int mp = 0; mp < MPW; ++mp)
            #pragma unroll
            for (int nt = 0; nt < NT; ++nt) C[mp][nt] = make_float4(0.f, 0.f, 0.f, 0.f);
        #pragma unroll
        for (int kt = 0; kt < KT; ++kt) {
            int kp0 = (kh * KT + kt) * 8 + tk;
            #pragma unroll
            for (int nt = 0; nt < NT; ++nt) {
                int n = nt * 8 + gid;
                uint2 u0 = hb[n * HLS2 + kp0];
                uint2 u1 = hb[n * HLS2 + kp0 + 4];
                #pragma unroll
                for (int mp = 0; mp < MPW; ++mp) {
                    mma_bf16(C[mp][nt], Ahi[mp][kt], u0.x, u1.x);
                    mma_bf16(C[mp][nt], Ahi[mp][kt], u0.y, u1.y);
                    mma_bf16(C[mp][nt], Alo[mp][kt], u0.x, u1.x);
                }
            }
        }
        float* gout = gso + kh * (GR * SG);
        #pragma unroll
        for (int mp = 0; mp < MPW; ++mp) {
            int m0 = (mg * MPW + mp) * 16;
            #pragma unroll
            for (int nt = 0; nt < NT; ++nt) {
                int col = nt * 8 + 2 * tk;
                *reinterpret_cast<float2*>(&gout[(m0 + gid) * SG + col]) =
                    make_float2(C[mp][nt].x, C[mp][nt].y);
                *reinterpret_cast<float2*>(&gout[(m0 + gid + 8) * SG + col]) =
                    make_float2(C[mp][nt].z, C[mp][nt].w);
            }
        }
    };

    // ---- P2: gates + state + st.async broadcast + xg prefetch --------------
    auto P2 = [&](int t, int halfidx) {
        const float* gp0 = gsm + halfidx * GSM_H;
        float s0[4], s1[4];
        #pragma unroll
        for (int g = 0; g < 4; ++g) {
            float a0 = xr[g].x, a1 = xr[g].y;
            int row = (g * JC + 2 * kl) * SG + pbl;
            #pragma unroll
            for (int khx = 0; khx < KH; ++khx) {
                const float* gp = gp0 + khx * (GR * SG);
                a0 += gp[row];
                a1 += gp[row + SG];
            }
            s0[g] = a0; s1[g] = a1;
        }
        float i0 = sigf(s0[0]), i1 = sigf(s1[0]);
        float f0 = sigf(s0[1]), f1 = sigf(s1[1]);
        float g0 = tanhe(s0[2]), g1 = tanhe(s1[2]);
        float o0 = sigf(s0[3]), o1 = sigf(s1[3]);
        cv0 = f0 * cv0 + i0 * g0;
        cv1 = f1 * cv1 + i1 * g1;
        float h0v = o0 * tanhe(cv0);
        float h1v = o1 * tanhe(cv1);

        uint32_t hi2, lo2;
        split_pack(h0v, h1v, hi2, lo2);

        if (t + 1 < TT) {   // broadcast (skipped on last step)
            const int idx = halfidx * 2 + ((t + 1) & 1);
            uint32_t off_mb  = (uint32_t)idx * 8;
            uint32_t off_dat = HL_OFF +
                (uint32_t)(((idx * HB + pbl) * HLS2 + kpg) * 8);
            #pragma unroll
            for (int p = 0; p < CL; ++p)
                st_async_v2(pbase[p] + off_dat, pbase[p] + off_mb, hi2, lo2);
        }

        if (out_seq)
            out_seq[((size_t)gb * TT + t) * (H / 2) + kpg] = make_uint2(hi2, lo2);
        if (out_final && t == TT - 1)
            out_final[(size_t)gb * (H / 2) + kpg] = make_uint2(hi2, lo2);

        // prefetch xg for t+1
        int tn = (t + 1 < TT) ? t + 1 : t;
        const float* xgt = xg + (size_t)tn * xg_ts + (size_t)gb * xg_bs;
        #pragma unroll
        for (int g = 0; g < 4; ++g)
            xr[g] = *reinterpret_cast<const float2*>(xgt + g * H + k0);
    };

    // ---- prologue + main loop ----------------------------------------------
    P1(0, 0, gsm, false);          // h(0)=0, slot prefilled
    __syncthreads();

    for (int t = 0; t < TT; ++t) {
        // even bracket: P2(A,t) || P1(B, t&1)
        if (!isB && act) P2(t, 0);
        P1(1, t & 1, gsm + GSM_H, t > 0);
        __syncthreads();
        // odd bracket: P2(B,t) || P1(A, (t+1)&1)
        if (isB && act) P2(t, 1);
        if (t + 1 < TT) P1(0, (t + 1) & 1, gsm, true);
        __syncthreads();
    }
    CLUSTER_SYNC_();   // keep peer smem alive until everyone is done
}

// enc: H=256, CL=8, KH=4, MPW=2   dec: H=128, CL=4, KH=2, MPW=1  (R8 config)
__global__ void __cluster_dims__(8, 1, 1) __launch_bounds__(512, 1)
lstm_enc(const float* __restrict__ Whh, const float* __restrict__ xg,
         size_t xg_bs, int xg_ts, uint2* __restrict__ out_seq,
         uint2* __restrict__ out_final)
{
    lstm_body<DHID, 8, 4, 2>(Whh, xg, xg_bs, xg_ts, out_seq, out_final);
}
__global__ void __cluster_dims__(4, 1, 1) __launch_bounds__(512, 1)
lstm_dec(const float* __restrict__ Whh, const float* __restrict__ xg,
         size_t xg_bs, int xg_ts, uint2* __restrict__ out_seq,
         uint2* __restrict__ out_final)
{
    lstm_body<DIN, 4, 2, 1>(Whh, xg, xg_bs, xg_ts, out_seq, out_final);
}

// ---------------------------------------------------------------------------
// Elementwise pack: fp32 pairs -> {bf16 hi x2, bf16 lo x2}
// ---------------------------------------------------------------------------
__global__ __launch_bounds__(256) void pack_hilo_kernel(
    const float* __restrict__ src, uint2* __restrict__ dst, int npairs)
{
    int i = blockIdx.x * 256 + threadIdx.x;
    if (i >= npairs) return;
    float2 f = reinterpret_cast<const float2*>(src)[i];
    uint32_t h2, l2;
    split_pack(f.x, f.y, h2, l2);
    dst[i] = make_uint2(h2, l2);
}

// ---------------------------------------------------------------------------
// Tensor-core GEMM, pre-packed bf16 hi/lo operands, REGISTER-STAGED PIPELINE:
// prologue loads tile 0 into registers; each k-iteration stores regs->smem,
// syncs, prefetches the NEXT tile's global loads (hidden under compute),
// computes, syncs. Global latency exposed once per CTA instead of per-iter.
// ---------------------------------------------------------------------------
__global__ __launch_bounds__(256, 2) void hgemm_pk(
    const uint2* __restrict__ Apk, const uint2* __restrict__ Bpk,
    const float* __restrict__ b1, const float* __restrict__ b2,
    float* __restrict__ C, int M, int N, int Kp)
{
    __shared__ uint2 As[128][18];
    __shared__ uint2 Bs[64][18];

    const int tid = threadIdx.x, wid = tid >> 5, lane = tid & 31;
    const int gid = lane >> 2, tk = lane & 3;
    const int bm = blockIdx.y * 128;
    const int bn = blockIdx.x * 64;
    const int wm = (wid & 3) * 32;
    const int wn = (wid >> 2) * 32;

    float4 Cc[2][4];
    #pragma unroll
    for (int mp = 0; mp < 2; ++mp)
        #pragma unroll
        for (int nt = 0; nt < 4; ++nt) Cc[mp][nt] = make_float4(0.f, 0.f, 0.f, 0.f);

    const int arow = tid >> 1, ac = (tid & 1) * 8;
    const int brow = tid >> 2, bc = (tid & 3) * 4;
    const uint2* Ap = Apk + (size_t)(bm + arow) * Kp + ac;
    const uint2* Bp = Bpk + (size_t)(bn + brow) * Kp + bc;

    uint4 ra[4], rb[2];
    #pragma unroll
    for (int v = 0; v < 4; ++v)
        ra[v] = __ldg(reinterpret_cast<const uint4*>(Ap + 2 * v));
    #pragma unroll
    for (int v = 0; v < 2; ++v)
        rb[v] = __ldg(reinterpret_cast<const uint4*>(Bp + 2 * v));

    for (int kb = 0; kb < Kp; kb += 16) {
        // stage registers -> smem
        #pragma unroll
        for (int v = 0; v < 4; ++v) {
            As[arow][ac + 2 * v]     = make_uint2(ra[v].x, ra[v].y);
            As[arow][ac + 2 * v + 1] = make_uint2(ra[v].z, ra[v].w);
        }
        #pragma unroll
        for (int v = 0; v < 2; ++v) {
            Bs[brow][bc + 2 * v]     = make_uint2(rb[v].x, rb[v].y);
            Bs[brow][bc + 2 * v + 1] = make_uint2(rb[v].z, rb[v].w);
        }
        __syncthreads();

        // prefetch next tile (latency hidden under compute below)
        if (kb + 16 < Kp) {
            #pragma unroll
            for (int v = 0; v < 4; ++v)
                ra[v] = __ldg(reinterpret_cast<const uint4*>(Ap + kb + 16 + 2 * v));
            #pragma unroll
            for (int v = 0; v < 2; ++v)
                rb[v] = __ldg(reinterpret_cast<const uint4*>(Bp + kb + 16 + 2 * v));
        }

        #pragma unroll
        for (int kt = 0; kt < 2; ++kt) {
            int kp = kt * 8 + tk;
            uint32_t Ah[2][4], Al[2][4];
            #pragma unroll
            for (int mp = 0; mp < 2; ++mp) {
                int r1 = wm + mp * 16 + gid;
                uint2 u00 = As[r1][kp],     u01 = As[r1][kp + 4];
                uint2 u10 = As[r1 + 8][kp], u11 = As[r1 + 8][kp + 4];
                Ah[mp][0] = u00.x; Ah[mp][1] = u10.x; Ah[mp][2] = u01.x; Ah[mp][3] = u11.x;
                Al[mp][0] = u00.y; Al[mp][1] = u10.y; Al[mp][2] = u01.y; Al[mp][3] = u11.y;
            }
            #pragma unroll
            for (int nt = 0; nt < 4; ++nt) {
                int n = wn + nt * 8 + gid;
                uint2 u0 = Bs[n][kp];
                uint2 u1 = Bs[n][kp + 4];
                #pragma unroll
                for (int mp = 0; mp < 2; ++mp) {
                    mma_bf16(Cc[mp][nt], Ah[mp], u0.x, u1.x);
                    mma_bf16(Cc[mp][nt], Ah[mp], u0.y, u1.y);
                    mma_bf16(Cc[mp][nt], Al[mp], u0.x, u1.x);
                }
            }
        }
        __syncthreads();
    }

    #pragma unroll
    for (int nt = 0; nt < 4; ++nt) {
        int n = bn + wn + nt * 8 + 2 * tk;
        float bb0 = b1[n]     + (b2 ? b2[n]     : 0.0f);
        float bb1 = b1[n + 1] + (b2 ? b2[n + 1] : 0.0f);
        #pragma unroll
        for (int mp = 0; mp < 2; ++mp) {
            int m1 = bm + wm + mp * 16 + gid;
            *reinterpret_cast<float2*>(C + (size_t)m1 * N + n) =
                make_float2(Cc[mp][nt].x + bb0, Cc[mp][nt].y + bb1);
            *reinterpret_cast<float2*>(C + (size_t)(m1 + 8) * N + n) =
                make_float2(Cc[mp][nt].z + bb0, Cc[mp][nt].w + bb1);
        }
    }
}

// ---------------------------------------------------------------------------
// Launch
// ---------------------------------------------------------------------------
// enc: 32 + 4*(16*132)*8 + 2*(4*128*18)*4 = 32+67584+73728 = 141344
static const int SMEM_ENC = 141344;
// dec: 32 + 4*(8*68)*8 + 2*(2*128*10)*4  = 32+17408+20480 =  37920
static const int SMEM_DEC = 37920;

static inline int cdiv(int a, int b) { return (a + b - 1) / b; }

extern "C" void kernel_launch(void* const* d_in, const int* in_sizes, int n_in,
                              void* d_out, int out_size)
{
    (void)in_sizes; (void)n_in; (void)out_size;
    const float* x        = (const float*)d_in[0];
    const float* e0_Wih   = (const float*)d_in[1];
    const float* e0_Whh   = (const float*)d_in[2];
    const float* e0_bih   = (const float*)d_in[3];
    const float* e0_bhh   = (const float*)d_in[4];
    const float* e1_Wih   = (const float*)d_in[5];
    const float* e1_Whh   = (const float*)d_in[6];
    const float* e1_bih   = (const float*)d_in[7];
    const float* e1_bhh   = (const float*)d_in[8];
    const float* d0_Wih   = (const float*)d_in[9];
    const float* d0_Whh   = (const float*)d_in[10];
    const float* d0_bih   = (const float*)d_in[11];
    const float* d0_bhh   = (const float*)d_in[12];
    const float* d1_Wih   = (const float*)d_in[13];
    const float* d1_Whh   = (const float*)d_in[14];
    const float* d1_bih   = (const float*)d_in[15];
    const float* d1_bhh   = (const float*)d_in[16];
    const float* out_W    = (const float*)d_in[17];
    const float* out_b    = (const float*)d_in[18];
    float* out = (float*)d_out;

    float *xg, *xgd0;
    uint2 *pk, *wpk, *hTpk;
    cudaGetSymbolAddress((void**)&xg,   g_xg);
    cudaGetSymbolAddress((void**)&pk,   g_pk);
    cudaGetSymbolAddress((void**)&wpk,  g_wpk);
    cudaGetSymbolAddress((void**)&hTpk, g_hTpk);
    cudaGetSymbolAddress((void**)&xgd0, g_xgd0);

    cudaFuncSetAttribute(lstm_enc,
                         cudaFuncAttributeMaxDynamicSharedMemorySize, SMEM_ENC);
    cudaFuncSetAttribute(lstm_dec,
                         cudaFuncAttributeMaxDynamicSharedMemorySize, SMEM_DEC);

    const int MT = BB * TT;  // 65536

    // 1) pack x, pack e0_Wih ; xg0 = x @ e0_Wih^T + b
    {
        int np = MT * DIN / 2;
        pack_hilo_kernel<<<cdiv(np, 256), 256>>>(x, pk, np);
        int nw = 4 * DHID * DIN / 2;
        pack_hilo_kernel<<<cdiv(nw, 256), 256>>>(e0_Wih, wpk, nw);
        hgemm_pk<<<dim3(4 * DHID / 64, MT / 128), 256>>>(
            pk, wpk, e0_bih, e0_bhh, xg, MT, 4 * DHID, DIN / 2);
    }
    // 2) enc0 recurrence -> e0 packed
    lstm_enc<<<128, 512, SMEM_ENC>>>(
        e0_Whh, xg, (size_t)TT * 4 * DHID, 4 * DHID, pk, nullptr);

    // 3) pack e1_Wih ; xg1 = e0 @ e1_Wih^T + b
    {
        int nw = 4 * DHID * DHID / 2;
        pack_hilo_kernel<<<cdiv(nw, 256), 256>>>(e1_Wih, wpk, nw);
        hgemm_pk<<<dim3(4 * DHID / 64, MT / 128), 256>>>(
            pk, wpk, e1_bih, e1_bhh, xg, MT, 4 * DHID, DHID / 2);
    }
    // 4) enc1 recurrence -> hT packed
    lstm_enc<<<128, 512, SMEM_ENC>>>(
        e1_Whh, xg, (size_t)TT * 4 * DHID, 4 * DHID, nullptr, hTpk);

    // 5) pack d0_Wih ; xgd0 = hT @ d0_Wih^T + b
    {
        int nw = 4 * DIN * DHID / 2;
        pack_hilo_kernel<<<cdiv(nw, 256), 256>>>(d0_Wih, wpk, nw);
        hgemm_pk<<<dim3(4 * DIN / 64, BB / 128), 256>>>(
            hTpk, wpk, d0_bih, d0_bhh, xgd0, BB, 4 * DIN, DHID / 2);
    }
    // 6) dec0 recurrence (t-stride 0) -> d0 packed
    lstm_dec<<<128, 512, SMEM_DEC>>>(
        d0_Whh, xgd0, (size_t)4 * DIN, 0, pk, nullptr);

    // 7) pack d1_Wih ; xgd1 = d0 @ d1_Wih^T + b
    {
        int nw = 4 * DIN * DIN / 2;
        pack_hilo_kernel<<<cdiv(nw, 256), 256>>>(d1_Wih, wpk, nw);
        hgemm_pk<<<dim3(4 * DIN / 64, MT / 128), 256>>>(
            pk, wpk, d1_bih, d1_bhh, xg, MT, 4 * DIN, DIN / 2);
    }
    // 8) dec1 recurrence -> d1 packed
    lstm_dec<<<128, 512, SMEM_DEC>>>(
        d1_Whh, xg, (size_t)TT * 4 * DIN, 4 * DIN, pk, nullptr);

    // 9) pack out_W ; out = d1 @ out_W^T + out_b
    {
        int nw = DIN * DIN / 2;
        pack_hilo_kernel<<<cdiv(nw, 256), 256>>>(out_W, wpk, nw);
        hgemm_pk<<<dim3(DIN / 64, MT / 128), 256>>>(
            pk, wpk, out_b, nullptr, out, MT, DIN, DIN / 2);
    }
}

// round 15
// speedup vs baseline: 1.2641x; 1.0156x over previous
#include <cuda_runtime.h>
#include <cuda_bf16.h>
#include <cstdint>
#include <cstddef>

#define BB   512
#define TT   128
#define DIN  128
#define DHID 256

// ---------------------------------------------------------------------------
// Scratch (device globals; no allocations allowed)
// ---------------------------------------------------------------------------
__device__ float g_xg  [(size_t)BB * TT * 4 * DHID];   // fp32 gate pre-activations
__device__ uint2 g_pk  [(size_t)BB * TT * DHID / 2];   // packed hi/lo activations
__device__ uint2 g_wpk [(size_t)4 * DHID * DHID / 2];  // packed weights (reused)
__device__ uint2 g_hTpk[(size_t)BB * DHID / 2];        // packed hT
__device__ float g_xgd0[(size_t)BB * 4 * DIN];         // dec0 xg (constant over t)

// ---------------------------------------------------------------------------
// Helpers
// ---------------------------------------------------------------------------
__device__ __forceinline__ float sigf(float x) { return 1.0f / (1.0f + __expf(-x)); }
__device__ __forceinline__ float tanhe(float x) {
    x = fminf(fmaxf(x, -15.0f), 15.0f);
    float e = __expf(-2.0f * x);
    return __fdividef(1.0f - e, 1.0f + e);
}
__device__ __forceinline__ uint32_t pack_bf16x2(float a, float b) {
    uint32_t r; asm("cvt.rn.bf16x2.f32 %0, %1, %2;" : "=r"(r) : "f"(b), "f"(a)); return r;
}
__device__ __forceinline__ void split_pack(float f0, float f1,
                                           uint32_t& hi2, uint32_t& lo2) {
    float h0 = __bfloat162float(__float2bfloat16(f0));
    float h1 = __bfloat162float(__float2bfloat16(f1));
    hi2 = pack_bf16x2(h0, h1);
    lo2 = pack_bf16x2(f0 - h0, f1 - h1);
}
__device__ __forceinline__ uint32_t smem_u32(const void* p) {
    uint32_t a;
    asm("{ .reg .u64 t; cvta.to.shared.u64 t, %1; cvt.u32.u64 %0, t; }" : "=r"(a) : "l"(p));
    return a;
}
__device__ __forceinline__ uint32_t cl_rank() {
    uint32_t r; asm("mov.u32 %0, %%cluster_ctarank;" : "=r"(r)); return r;
}
__device__ __forceinline__ uint32_t mapa_u32(uint32_t addr, uint32_t rank) {
    uint32_t r;
    asm("mapa.shared::cluster.u32 %0, %1, %2;" : "=r"(r) : "r"(addr), "r"(rank));
    return r;
}
#define CLUSTER_SYNC_() do { \
    asm volatile("barrier.cluster.arrive.aligned;" ::: "memory"); \
    asm volatile("barrier.cluster.wait.aligned;"   ::: "memory"); \
} while (0)

__device__ __forceinline__ void mb_init(uint32_t mb, uint32_t cnt) {
    asm volatile("mbarrier.init.shared.b64 [%0], %1;" :: "r"(mb), "r"(cnt) : "memory");
}
__device__ __forceinline__ void mb_arrive_tx(uint32_t mb, uint32_t tx) {
    asm volatile("mbarrier.arrive.expect_tx.shared.b64 _, [%0], %1;"
                 :: "r"(mb), "r"(tx) : "memory");
}
__device__ __forceinline__ void mb_wait(uint32_t mb, uint32_t parity) {
    asm volatile(
        "{\n\t.reg .pred P;\n\t"
        "WL_%=:\n\t"
        "mbarrier.try_wait.parity.acquire.cluster.shared::cta.b64 P, [%0], %1, 0x989680;\n\t"
        "@P bra.uni WD_%=;\n\t"
        "bra.uni WL_%=;\n\t"
        "WD_%=:\n\t}"
        :: "r"(mb), "r"(parity) : "memory");
}
// async store to (possibly remote) CTA smem, signaling its mbarrier tx count
__device__ __forceinline__ void st_async_v2(uint32_t raddr, uint32_t rmbar,
                                            uint32_t a, uint32_t b) {
    asm volatile(
        "st.async.shared::cluster.mbarrier::complete_tx::bytes.v2.b32 [%0], {%2,%3}, [%1];"
        :: "r"(raddr), "r"(rmbar), "r"(a), "r"(b) : "memory");
}

__device__ __forceinline__ void mma_bf16(float4& c, const uint32_t a[4],
                                         uint32_t b0, uint32_t b1) {
    asm volatile(
        "mma.sync.aligned.m16n8k16.row.col.f32.bf16.bf16.f32 "
        "{%0,%1,%2,%3}, {%4,%5,%6,%7}, {%8,%9}, {%0,%1,%2,%3};"
        : "+f"(c.x), "+f"(c.y), "+f"(c.z), "+f"(c.w)
        : "r"(a[0]), "r"(a[1]), "r"(a[2]), "r"(a[3]), "r"(b0), "r"(b1));
}

// ---------------------------------------------------------------------------
// Recurrent LSTM body — EXACT R8 shape (protected optimum): bf16 hi/lo tensor
// cores, two-half pipeline, st.async + mbarrier-tx h exchange.
// ---------------------------------------------------------------------------
template <int H, int CL, int KH, int MPW>
__device__ __forceinline__ void lstm_body(
    const float* __restrict__ Whh, const float* __restrict__ xg,
    size_t xg_bs, int xg_ts,
    uint2* __restrict__ out_seq, uint2* __restrict__ out_final)
{
    constexpr int K    = H;
    constexpr int JC   = H / CL;
    constexpr int GR   = 4 * H / CL;
    constexpr int KT   = (K / 16) / KH;
    constexpr int MG   = (GR / 16) / MPW;
    static_assert(MG * KH == 16, "16 warps");
    constexpr int Bt   = 4 * CL;
    constexpr int HB   = Bt / 2;            // half-batch
    constexpr int NT   = HB / 8;            // n8 tiles per half
    static_assert(NT >= 1, "NT");
    constexpr int HLS2 = K / 2 + 4;         // uint2 stride per b row
    static_assert(HLS2 % 16 == 4, "banks");
    constexpr int SG   = HB + 2;
    constexpr int HSLOT = HB * HLS2;        // uint2 per (half,slot)
    constexpr int GSM_H = KH * GR * SG;
    constexpr uint32_t TXB = (uint32_t)HB * (K / 2) * 8;  // bytes per mbar phase
    constexpr int HL_OFF = 32;              // mbar block at smem start

    extern __shared__ char smraw[];
    uint2* hl  = reinterpret_cast<uint2*>(smraw + HL_OFF);            // [4][HB][HLS2]
    float* gsm = reinterpret_cast<float*>(smraw + HL_OFF + (size_t)4 * HSLOT * 8);

    const int tid = threadIdx.x, wid = tid >> 5, lane = tid & 31;
    const int gid = lane >> 2, tk = lane & 3;
    const uint32_t r = cl_rank();
    const int b0 = (blockIdx.x / CL) * Bt;
    const uint32_t sbase = smem_u32(smraw);

    const int mg = wid / KH, kh = wid % KH;

    // ---- preload Whh fragments -------------------------------------------
    uint32_t Ahi[MPW][KT][4], Alo[MPW][KT][4];
    #pragma unroll
    for (int mp = 0; mp < MPW; ++mp) {
        int m0 = (mg * MPW + mp) * 16;
        int j1 = m0 + gid, j2 = j1 + 8;
        const float* w1 = Whh + (size_t)((j1 / JC) * H + r * JC + (j1 % JC)) * K;
        const float* w2 = Whh + (size_t)((j2 / JC) * H + r * JC + (j2 % JC)) * K;
        #pragma unroll
        for (int kt = 0; kt < KT; ++kt) {
            int ka = (kh * KT + kt) * 16 + 2 * tk;
            split_pack(w1[ka],     w1[ka + 1], Ahi[mp][kt][0], Alo[mp][kt][0]);
            split_pack(w2[ka],     w2[ka + 1], Ahi[mp][kt][1], Alo[mp][kt][1]);
            split_pack(w1[ka + 8], w1[ka + 9], Ahi[mp][kt][2], Alo[mp][kt][2]);
            split_pack(w2[ka + 8], w2[ka + 9], Ahi[mp][kt][3], Alo[mp][kt][3]);
        }
    }
    // ---- init mbarriers + arm phase 0, zero h slots ------------------------
    if (tid == 0) {
        #pragma unroll
        for (int i = 0; i < 4; ++i) {
            mb_init(sbase + i * 8, 1);
            mb_arrive_tx(sbase + i * 8, TXB);
        }
    }
    for (int i = tid; i < 4 * HSLOT * 2; i += 512)
        reinterpret_cast<uint32_t*>(hl)[i] = 0u;
    __syncthreads();
    CLUSTER_SYNC_();          // all mbarriers live before any st.async

    // peer smem bases
    uint32_t pbase[CL];
    #pragma unroll
    for (int p = 0; p < CL; ++p) pbase[p] = mapa_u32(sbase, (uint32_t)p);

    // ---- phase-2 identity ---------------------------------------------------
    constexpr int ITh = HB * (JC / 2);
    static_assert(ITh <= 256, "P2 items fit half the threads");
    const bool isB = tid >= 256;
    const int  lt  = isB ? tid - 256 : tid;
    const bool act = lt < ITh;
    const int  pbl = lt / (JC / 2);
    const int  kl  = lt % (JC / 2);
    const int  k0  = r * JC + 2 * kl;
    const int  kpg = (r * JC) / 2 + kl;
    const int  gb  = b0 + (isB ? HB : 0) + pbl;
    float cv0 = 0.0f, cv1 = 0.0f;
    uint32_t phbits = 0;     // per-mbar phase parity
    float2 xr[4];
    if (act) {
        const float* xgt = xg + (size_t)gb * xg_bs;   // t = 0
        #pragma unroll
        for (int g = 0; g < 4; ++g)
            xr[g] = *reinterpret_cast<const float2*>(xgt + g * H + k0);
    }

    // ---- P1: bf16 MMAs for one (half, slot) --------------------------------
    auto P1 = [&](int halfidx, int slot, float* gso, bool dowait) {
        const int idx = halfidx * 2 + slot;
        if (dowait) {
            uint32_t mb = sbase + idx * 8;
            mb_wait(mb, (phbits >> idx) & 1u);
            phbits ^= (1u << idx);
            if (tid == 0) mb_arrive_tx(mb, TXB);   // re-arm next phase
        }
        const uint2* hb = hl + (size_t)idx * HSLOT;
        float4 C[MPW][NT];
        #pragma unroll
        for (int mp = 0; mp < MPW; ++mp)
            #pragma unroll
            for (int nt = 0; nt < NT; ++nt) C[mp][nt] = make_float4(0.f, 0.f, 0.f, 0.f);
        #pragma unroll
        for (int kt = 0; kt < KT; ++kt) {
            int kp0 = (kh * KT + kt) * 8 + tk;
            #pragma unroll
            for (int nt = 0; nt < NT; ++nt) {
                int n = nt * 8 + gid;
                uint2 u0 = hb[n * HLS2 + kp0];
                uint2 u1 = hb[n * HLS2 + kp0 + 4];
                #pragma unroll
                for (int mp = 0; mp < MPW; ++mp) {
                    mma_bf16(C[mp][nt], Ahi[mp][kt], u0.x, u1.x);
                    mma_bf16(C[mp][nt], Ahi[mp][kt], u0.y, u1.y);
                    mma_bf16(C[mp][nt], Alo[mp][kt], u0.x, u1.x);
                }
            }
        }
        float* gout = gso + kh * (GR * SG);
        #pragma unroll
        for (int mp = 0; mp < MPW; ++mp) {
            int m0 = (mg * MPW + mp) * 16;
            #pragma unroll
            for (int nt = 0; nt < NT; ++nt) {
                int col = nt * 8 + 2 * tk;
                *reinterpret_cast<float2*>(&gout[(m0 + gid) * SG + col]) =
                    make_float2(C[mp][nt].x, C[mp][nt].y);
                *reinterpret_cast<float2*>(&gout[(m0 + gid + 8) * SG + col]) =
                    make_float2(C[mp][nt].z, C[mp][nt].w);
            }
        }
    };

    // ---- P2: gates + state + st.async broadcast + xg prefetch --------------
    auto P2 = [&](int t, int halfidx) {
        const float* gp0 = gsm + halfidx * GSM_H;
        float s0[4], s1[4];
        #pragma unroll
        for (int g = 0; g < 4; ++g) {
            float a0 = xr[g].x, a1 = xr[g].y;
            int row = (g * JC + 2 * kl) * SG + pbl;
            #pragma unroll
            for (int khx = 0; khx < KH; ++khx) {
                const float* gp = gp0 + khx * (GR * SG);
                a0 += gp[row];
                a1 += gp[row + SG];
            }
            s0[g] = a0; s1[g] = a1;
        }
        float i0 = sigf(s0[0]), i1 = sigf(s1[0]);
        float f0 = sigf(s0[1]), f1 = sigf(s1[1]);
        float g0 = tanhe(s0[2]), g1 = tanhe(s1[2]);
        float o0 = sigf(s0[3]), o1 = sigf(s1[3]);
        cv0 = f0 * cv0 + i0 * g0;
        cv1 = f1 * cv1 + i1 * g1;
        float h0v = o0 * tanhe(cv0);
        float h1v = o1 * tanhe(cv1);

        uint32_t hi2, lo2;
        split_pack(h0v, h1v, hi2, lo2);

        if (t + 1 < TT) {   // broadcast (skipped on last step)
            const int idx = halfidx * 2 + ((t + 1) & 1);
            uint32_t off_mb  = (uint32_t)idx * 8;
            uint32_t off_dat = HL_OFF +
                (uint32_t)(((idx * HB + pbl) * HLS2 + kpg) * 8);
            #pragma unroll
            for (int p = 0; p < CL; ++p)
                st_async_v2(pbase[p] + off_dat, pbase[p] + off_mb, hi2, lo2);
        }

        if (out_seq)
            out_seq[((size_t)gb * TT + t) * (H / 2) + kpg] = make_uint2(hi2, lo2);
        if (out_final && t == TT - 1)
            out_final[(size_t)gb * (H / 2) + kpg] = make_uint2(hi2, lo2);

        // prefetch xg for t+1
        int tn = (t + 1 < TT) ? t + 1 : t;
        const float* xgt = xg + (size_t)tn * xg_ts + (size_t)gb * xg_bs;
        #pragma unroll
        for (int g = 0; g < 4; ++g)
            xr[g] = *reinterpret_cast<const float2*>(xgt + g * H + k0);
    };

    // ---- prologue + main loop ----------------------------------------------
    P1(0, 0, gsm, false);          // h(0)=0, slot prefilled
    __syncthreads();

    for (int t = 0; t < TT; ++t) {
        // even bracket: P2(A,t) || P1(B, t&1)
        if (!isB && act) P2(t, 0);
        P1(1, t & 1, gsm + GSM_H, t > 0);
        __syncthreads();
        // odd bracket: P2(B,t) || P1(A, (t+1)&1)
        if (isB && act) P2(t, 1);
        if (t + 1 < TT) P1(0, (t + 1) & 1, gsm, true);
        __syncthreads();
    }
    CLUSTER_SYNC_();   // keep peer smem alive until everyone is done
}

// enc: H=256, CL=8, KH=4, MPW=2   dec: H=128, CL=4, KH=2, MPW=1  (R8 config)
__global__ void __cluster_dims__(8, 1, 1) __launch_bounds__(512, 1)
lstm_enc(const float* __restrict__ Whh, const float* __restrict__ xg,
         size_t xg_bs, int xg_ts, uint2* __restrict__ out_seq,
         uint2* __restrict__ out_final)
{
    lstm_body<DHID, 8, 4, 2>(Whh, xg, xg_bs, xg_ts, out_seq, out_final);
}
__global__ void __cluster_dims__(4, 1, 1) __launch_bounds__(512, 1)
lstm_dec(const float* __restrict__ Whh, const float* __restrict__ xg,
         size_t xg_bs, int xg_ts, uint2* __restrict__ out_seq,
         uint2* __restrict__ out_final)
{
    lstm_body<DIN, 4, 2, 1>(Whh, xg, xg_bs, xg_ts, out_seq, out_final);
}

// ---------------------------------------------------------------------------
// Elementwise pack: fp32 pairs -> {bf16 hi x2, bf16 lo x2}
// ---------------------------------------------------------------------------
__global__ __launch_bounds__(256) void pack_hilo_kernel(
    const float* __restrict__ src, uint2* __restrict__ dst, int npairs)
{
    int i = blockIdx.x * 256 + threadIdx.x;
    if (i >= npairs) return;
    float2 f = reinterpret_cast<const float2*>(src)[i];
    uint32_t h2, l2;
    split_pack(f.x, f.y, h2, l2);
    dst[i] = make_uint2(h2, l2);
}

// ---------------------------------------------------------------------------
// Tensor-core GEMM, pre-packed bf16 hi/lo, BM=128 BN=128 BK=32, 512 threads
// (16 warps = 4m x 4n, warp tile 32x32), register-staged global pipeline.
// A-tile traffic halved vs BN=64; CTA count halved.
// ---------------------------------------------------------------------------
__global__ __launch_bounds__(512, 1) void hgemm_pk(
    const uint2* __restrict__ Apk,   // [M][Kp]
    const uint2* __restrict__ Bpk,   // [N][Kp]
    const float* __restrict__ b1, const float* __restrict__ b2,
    float* __restrict__ C, int M, int N, int Kp)
{
    __shared__ uint2 As[128][18];
    __shared__ uint2 Bs[128][18];

    const int tid = threadIdx.x, wid = tid >> 5, lane = tid & 31;
    const int gid = lane >> 2, tk = lane & 3;
    const int bm = blockIdx.y * 128;
    const int bn = blockIdx.x * 128;
    const int wm = (wid & 3) * 32;
    const int wn = (wid >> 2) * 32;

    float4 Cc[2][4];
    #pragma unroll
    for (int mp = 0; mp < 2; ++mp)
        #pragma unroll
        for (int nt = 0; nt < 4; ++nt) Cc[mp][nt] = make_float4(0.f, 0.f, 0.f, 0.f);

    const int row = tid >> 2;              // 0..127
    const int cq  = (tid & 3) * 4;         // uint2 col: 0,4,8,12
    const uint2* Ap = Apk + (size_t)(bm + row) * Kp + cq;
    const uint2* Bp = Bpk + (size_t)(bn + row) * Kp + cq;

    uint4 ra[2], rb[2];
    #pragma unroll
    for (int v = 0; v < 2; ++v) {
        ra[v] = __ldg(reinterpret_cast<const uint4*>(Ap + 2 * v));
        rb[v] = __ldg(reinterpret_cast<const uint4*>(Bp + 2 * v));
    }

    for (int kb = 0; kb < Kp; kb += 16) {
        // stage registers -> smem
        #pragma unroll
        for (int v = 0; v < 2; ++v) {
            As[row][cq + 2 * v]     = make_uint2(ra[v].x, ra[v].y);
            As[row][cq + 2 * v + 1] = make_uint2(ra[v].z, ra[v].w);
            Bs[row][cq + 2 * v]     = make_uint2(rb[v].x, rb[v].y);
            Bs[row][cq + 2 * v + 1] = make_uint2(rb[v].z, rb[v].w);
        }
        __syncthreads();

        // prefetch next tile (latency hidden under compute below)
        if (kb + 16 < Kp) {
            #pragma unroll
            for (int v = 0; v < 2; ++v) {
                ra[v] = __ldg(reinterpret_cast<const uint4*>(Ap + kb + 16 + 2 * v));
                rb[v] = __ldg(reinterpret_cast<const uint4*>(Bp + kb + 16 + 2 * v));
            }
        }

        #pragma unroll
        for (int kt = 0; kt < 2; ++kt) {
            int kp = kt * 8 + tk;
            uint32_t Ah[2][4], Al[2][4];
            #pragma unroll
            for (int mp = 0; mp < 2; ++mp) {
                int r1 = wm + mp * 16 + gid;
                uint2 u00 = As[r1][kp],     u01 = As[r1][kp + 4];
                uint2 u10 = As[r1 + 8][kp], u11 = As[r1 + 8][kp + 4];
                Ah[mp][0] = u00.x; Ah[mp][1] = u10.x; Ah[mp][2] = u01.x; Ah[mp][3] = u11.x;
                Al[mp][0] = u00.y; Al[mp][1] = u10.y; Al[mp][2] = u01.y; Al[mp][3] = u11.y;
            }
            #pragma unroll
            for (int nt = 0; nt < 4; ++nt) {
                int n = wn + nt * 8 + gid;
                uint2 u0 = Bs[n][kp];
                uint2 u1 = Bs[n][kp + 4];
                #pragma unroll
                for (int mp = 0; mp < 2; ++mp) {
                    mma_bf16(Cc[mp][nt], Ah[mp], u0.x, u1.x);
                    mma_bf16(Cc[mp][nt], Ah[mp], u0.y, u1.y);
                    mma_bf16(Cc[mp][nt], Al[mp], u0.x, u1.x);
                }
            }
        }
        __syncthreads();
    }

    #pragma unroll
    for (int nt = 0; nt < 4; ++nt) {
        int n = bn + wn + nt * 8 + 2 * tk;
        float bb0 = b1[n]     + (b2 ? b2[n]     : 0.0f);
        float bb1 = b1[n + 1] + (b2 ? b2[n + 1] : 0.0f);
        #pragma unroll
        for (int mp = 0; mp < 2; ++mp) {
            int m1 = bm + wm + mp * 16 + gid;
            *reinterpret_cast<float2*>(C + (size_t)m1 * N + n) =
                make_float2(Cc[mp][nt].x + bb0, Cc[mp][nt].y + bb1);
            *reinterpret_cast<float2*>(C + (size_t)(m1 + 8) * N + n) =
                make_float2(Cc[mp][nt].z + bb0, Cc[mp][nt].w + bb1);
        }
    }
}

// ---------------------------------------------------------------------------
// Launch
// ---------------------------------------------------------------------------
// enc: 32 + 4*(16*132)*8 + 2*(4*128*18)*4 = 32+67584+73728 = 141344
static const int SMEM_ENC = 141344;
// dec: 32 + 4*(8*68)*8 + 2*(2*128*10)*4  = 32+17408+20480 =  37920
static const int SMEM_DEC = 37920;

static inline int cdiv(int a, int b) { return (a + b - 1) / b; }

extern "C" void kernel_launch(void* const* d_in, const int* in_sizes, int n_in,
                              void* d_out, int out_size)
{
    (void)in_sizes; (void)n_in; (void)out_size;
    const float* x        = (const float*)d_in[0];
    const float* e0_Wih   = (const float*)d_in[1];
    const float* e0_Whh   = (const float*)d_in[2];
    const float* e0_bih   = (const float*)d_in[3];
    const float* e0_bhh   = (const float*)d_in[4];
    const float* e1_Wih   = (const float*)d_in[5];
    const float* e1_Whh   = (const float*)d_in[6];
    const float* e1_bih   = (const float*)d_in[7];
    const float* e1_bhh   = (const float*)d_in[8];
    const float* d0_Wih   = (const float*)d_in[9];
    const float* d0_Whh   = (const float*)d_in[10];
    const float* d0_bih   = (const float*)d_in[11];
    const float* d0_bhh   = (const float*)d_in[12];
    const float* d1_Wih   = (const float*)d_in[13];
    const float* d1_Whh   = (const float*)d_in[14];
    const float* d1_bih   = (const float*)d_in[15];
    const float* d1_bhh   = (const float*)d_in[16];
    const float* out_W    = (const float*)d_in[17];
    const float* out_b    = (const float*)d_in[18];
    float* out = (float*)d_out;

    float *xg, *xgd0;
    uint2 *pk, *wpk, *hTpk;
    cudaGetSymbolAddress((void**)&xg,   g_xg);
    cudaGetSymbolAddress((void**)&pk,   g_pk);
    cudaGetSymbolAddress((void**)&wpk,  g_wpk);
    cudaGetSymbolAddress((void**)&hTpk, g_hTpk);
    cudaGetSymbolAddress((void**)&xgd0, g_xgd0);

    cudaFuncSetAttribute(lstm_enc,
                         cudaFuncAttributeMaxDynamicSharedMemorySize, SMEM_ENC);
    cudaFuncSetAttribute(lstm_dec,
                         cudaFuncAttributeMaxDynamicSharedMemorySize, SMEM_DEC);

    const int MT = BB * TT;  // 65536

    // 1) pack x, pack e0_Wih ; xg0 = x @ e0_Wih^T + b
    {
        int np = MT * DIN / 2;
        pack_hilo_kernel<<<cdiv(np, 256), 256>>>(x, pk, np);
        int nw = 4 * DHID * DIN / 2;
        pack_hilo_kernel<<<cdiv(nw, 256), 256>>>(e0_Wih, wpk, nw);
        hgemm_pk<<<dim3(4 * DHID / 128, MT / 128), 512>>>(
            pk, wpk, e0_bih, e0_bhh, xg, MT, 4 * DHID, DIN / 2);
    }
    // 2) enc0 recurrence -> e0 packed
    lstm_enc<<<128, 512, SMEM_ENC>>>(
        e0_Whh, xg, (size_t)TT * 4 * DHID, 4 * DHID, pk, nullptr);

    // 3) pack e1_Wih ; xg1 = e0 @ e1_Wih^T + b
    {
        int nw = 4 * DHID * DHID / 2;
        pack_hilo_kernel<<<cdiv(nw, 256), 256>>>(e1_Wih, wpk, nw);
        hgemm_pk<<<dim3(4 * DHID / 128, MT / 128), 512>>>(
            pk, wpk, e1_bih, e1_bhh, xg, MT, 4 * DHID, DHID / 2);
    }
    // 4) enc1 recurrence -> hT packed
    lstm_enc<<<128, 512, SMEM_ENC>>>(
        e1_Whh, xg, (size_t)TT * 4 * DHID, 4 * DHID, nullptr, hTpk);

    // 5) pack d0_Wih ; xgd0 = hT @ d0_Wih^T + b
    {
        int nw = 4 * DIN * DHID / 2;
        pack_hilo_kernel<<<cdiv(nw, 256), 256>>>(d0_Wih, wpk, nw);
        hgemm_pk<<<dim3(4 * DIN / 128, BB / 128), 512>>>(
            hTpk, wpk, d0_bih, d0_bhh, xgd0, BB, 4 * DIN, DHID / 2);
    }
    // 6) dec0 recurrence (t-stride 0) -> d0 packed
    lstm_dec<<<128, 512, SMEM_DEC>>>(
        d0_Whh, xgd0, (size_t)4 * DIN, 0, pk, nullptr);

    // 7) pack d1_Wih ; xgd1 = d0 @ d1_Wih^T + b
    {
        int nw = 4 * DIN * DIN / 2;
        pack_hilo_kernel<<<cdiv(nw, 256), 256>>>(d1_Wih, wpk, nw);
        hgemm_pk<<<dim3(4 * DIN / 128, MT / 128), 512>>>(
            pk, wpk, d1_bih, d1_bhh, xg, MT, 4 * DIN, DIN / 2);
    }
    // 8) dec1 recurrence -> d1 packed
    lstm_dec<<<128, 512, SMEM_DEC>>>(
        d1_Whh, xg, (size_t)TT * 4 * DIN, 4 * DIN, pk, nullptr);

    // 9) pack out_W ; out = d1 @ out_W^T + out_b
    {
        int nw = DIN * DIN / 2;
        pack_hilo_kernel<<<cdiv(nw, 256), 256>>>(out_W, wpk, nw);
        hgemm_pk<<<dim3(DIN / 128, MT / 128), 512>>>(
            pk, wpk, out_b, nullptr, out, MT, DIN, DIN / 2);
    }
}

// round 16
// speedup vs baseline: 1.2646x; 1.0004x over previous
#include <cuda_runtime.h>
#include <cuda_bf16.h>
#include <cstdint>
#include <cstddef>

#define BB   512
#define TT   128
#define DIN  128
#define DHID 256

// ---------------------------------------------------------------------------
// Scratch (device globals; no allocations allowed)
// ---------------------------------------------------------------------------
__device__ float g_xg  [(size_t)BB * TT * 4 * DHID];   // fp32 gate pre-activations
__device__ uint2 g_pk  [(size_t)BB * TT * DHID / 2];   // packed hi/lo activations
__device__ uint2 g_wpk [(size_t)4 * DHID * DHID / 2];  // packed weights (reused)
__device__ uint2 g_hTpk[(size_t)BB * DHID / 2];        // packed hT
__device__ float g_xgd0[(size_t)BB * 4 * DIN];         // dec0 xg (constant over t)

// ---------------------------------------------------------------------------
// Helpers
// ---------------------------------------------------------------------------
__device__ __forceinline__ float sigf(float x) { return 1.0f / (1.0f + __expf(-x)); }
__device__ __forceinline__ float tanhe(float x) {
    x = fminf(fmaxf(x, -15.0f), 15.0f);
    float e = __expf(-2.0f * x);
    return __fdividef(1.0f - e, 1.0f + e);
}
__device__ __forceinline__ uint32_t pack_bf16x2(float a, float b) {
    uint32_t r; asm("cvt.rn.bf16x2.f32 %0, %1, %2;" : "=r"(r) : "f"(b), "f"(a)); return r;
}
__device__ __forceinline__ void split_pack(float f0, float f1,
                                           uint32_t& hi2, uint32_t& lo2) {
    float h0 = __bfloat162float(__float2bfloat16(f0));
    float h1 = __bfloat162float(__float2bfloat16(f1));
    hi2 = pack_bf16x2(h0, h1);
    lo2 = pack_bf16x2(f0 - h0, f1 - h1);
}
__device__ __forceinline__ uint32_t smem_u32(const void* p) {
    uint32_t a;
    asm("{ .reg .u64 t; cvta.to.shared.u64 t, %1; cvt.u32.u64 %0, t; }" : "=r"(a) : "l"(p));
    return a;
}
__device__ __forceinline__ uint32_t cl_rank() {
    uint32_t r; asm("mov.u32 %0, %%cluster_ctarank;" : "=r"(r)); return r;
}
__device__ __forceinline__ uint32_t mapa_u32(uint32_t addr, uint32_t rank) {
    uint32_t r;
    asm("mapa.shared::cluster.u32 %0, %1, %2;" : "=r"(r) : "r"(addr), "r"(rank));
    return r;
}
#define CLUSTER_SYNC_() do { \
    asm volatile("barrier.cluster.arrive.aligned;" ::: "memory"); \
    asm volatile("barrier.cluster.wait.aligned;"   ::: "memory"); \
} while (0)

__device__ __forceinline__ void mb_init(uint32_t mb, uint32_t cnt) {
    asm volatile("mbarrier.init.shared.b64 [%0], %1;" :: "r"(mb), "r"(cnt) : "memory");
}
__device__ __forceinline__ void mb_arrive_tx(uint32_t mb, uint32_t tx) {
    asm volatile("mbarrier.arrive.expect_tx.shared.b64 _, [%0], %1;"
                 :: "r"(mb), "r"(tx) : "memory");
}
__device__ __forceinline__ void mb_wait(uint32_t mb, uint32_t parity) {
    asm volatile(
        "{\n\t.reg .pred P;\n\t"
        "WL_%=:\n\t"
        "mbarrier.try_wait.parity.acquire.cluster.shared::cta.b64 P, [%0], %1, 0x989680;\n\t"
        "@P bra.uni WD_%=;\n\t"
        "bra.uni WL_%=;\n\t"
        "WD_%=:\n\t}"
        :: "r"(mb), "r"(parity) : "memory");
}
// async store to (possibly remote) CTA smem, signaling its mbarrier tx count
__device__ __forceinline__ void st_async_v2(uint32_t raddr, uint32_t rmbar,
                                            uint32_t a, uint32_t b) {
    asm volatile(
        "st.async.shared::cluster.mbarrier::complete_tx::bytes.v2.b32 [%0], {%2,%3}, [%1];"
        :: "r"(raddr), "r"(rmbar), "r"(a), "r"(b) : "memory");
}

__device__ __forceinline__ void mma_bf16(float4& c, const uint32_t a[4],
                                         uint32_t b0, uint32_t b1) {
    asm volatile(
        "mma.sync.aligned.m16n8k16.row.col.f32.bf16.bf16.f32 "
        "{%0,%1,%2,%3}, {%4,%5,%6,%7}, {%8,%9}, {%0,%1,%2,%3};"
        : "+f"(c.x), "+f"(c.y), "+f"(c.z), "+f"(c.w)
        : "r"(a[0]), "r"(a[1]), "r"(a[2]), "r"(a[3]), "r"(b0), "r"(b1));
}

// ---------------------------------------------------------------------------
// Recurrent LSTM body — EXACT R8 shape (protected optimum): bf16 hi/lo tensor
// cores, two-half pipeline, st.async + mbarrier-tx h exchange.
// ---------------------------------------------------------------------------
template <int H, int CL, int KH, int MPW>
__device__ __forceinline__ void lstm_body(
    const float* __restrict__ Whh, const float* __restrict__ xg,
    size_t xg_bs, int xg_ts,
    uint2* __restrict__ out_seq, uint2* __restrict__ out_final)
{
    constexpr int K    = H;
    constexpr int JC   = H / CL;
    constexpr int GR   = 4 * H / CL;
    constexpr int KT   = (K / 16) / KH;
    constexpr int MG   = (GR / 16) / MPW;
    static_assert(MG * KH == 16, "16 warps");
    constexpr int Bt   = 4 * CL;
    constexpr int HB   = Bt / 2;            // half-batch
    constexpr int NT   = HB / 8;            // n8 tiles per half
    static_assert(NT >= 1, "NT");
    constexpr int HLS2 = K / 2 + 4;         // uint2 stride per b row
    static_assert(HLS2 % 16 == 4, "banks");
    constexpr int SG   = HB + 2;
    constexpr int HSLOT = HB * HLS2;        // uint2 per (half,slot)
    constexpr int GSM_H = KH * GR * SG;
    constexpr uint32_t TXB = (uint32_t)HB * (K / 2) * 8;  // bytes per mbar phase
    constexpr int HL_OFF = 32;              // mbar block at smem start

    extern __shared__ char smraw[];
    uint2* hl  = reinterpret_cast<uint2*>(smraw + HL_OFF);            // [4][HB][HLS2]
    float* gsm = reinterpret_cast<float*>(smraw + HL_OFF + (size_t)4 * HSLOT * 8);

    const int tid = threadIdx.x, wid = tid >> 5, lane = tid & 31;
    const int gid = lane >> 2, tk = lane & 3;
    const uint32_t r = cl_rank();
    const int b0 = (blockIdx.x / CL) * Bt;
    const uint32_t sbase = smem_u32(smraw);

    const int mg = wid / KH, kh = wid % KH;

    // ---- preload Whh fragments -------------------------------------------
    uint32_t Ahi[MPW][KT][4], Alo[MPW][KT][4];
    #pragma unroll
    for (int mp = 0; mp < MPW; ++mp) {
        int m0 = (mg * MPW + mp) * 16;
        int j1 = m0 + gid, j2 = j1 + 8;
        const float* w1 = Whh + (size_t)((j1 / JC) * H + r * JC + (j1 % JC)) * K;
        const float* w2 = Whh + (size_t)((j2 / JC) * H + r * JC + (j2 % JC)) * K;
        #pragma unroll
        for (int kt = 0; kt < KT; ++kt) {
            int ka = (kh * KT + kt) * 16 + 2 * tk;
            split_pack(w1[ka],     w1[ka + 1], Ahi[mp][kt][0], Alo[mp][kt][0]);
            split_pack(w2[ka],     w2[ka + 1], Ahi[mp][kt][1], Alo[mp][kt][1]);
            split_pack(w1[ka + 8], w1[ka + 9], Ahi[mp][kt][2], Alo[mp][kt][2]);
            split_pack(w2[ka + 8], w2[ka + 9], Ahi[mp][kt][3], Alo[mp][kt][3]);
        }
    }
    // ---- init mbarriers + arm phase 0, zero h slots ------------------------
    if (tid == 0) {
        #pragma unroll
        for (int i = 0; i < 4; ++i) {
            mb_init(sbase + i * 8, 1);
            mb_arrive_tx(sbase + i * 8, TXB);
        }
    }
    for (int i = tid; i < 4 * HSLOT * 2; i += 512)
        reinterpret_cast<uint32_t*>(hl)[i] = 0u;
    __syncthreads();
    CLUSTER_SYNC_();          // all mbarriers live before any st.async

    // peer smem bases
    uint32_t pbase[CL];
    #pragma unroll
    for (int p = 0; p < CL; ++p) pbase[p] = mapa_u32(sbase, (uint32_t)p);

    // ---- phase-2 identity ---------------------------------------------------
    constexpr int ITh = HB * (JC / 2);
    static_assert(ITh <= 256, "P2 items fit half the threads");
    const bool isB = tid >= 256;
    const int  lt  = isB ? tid - 256 : tid;
    const bool act = lt < ITh;
    const int  pbl = lt / (JC / 2);
    const int  kl  = lt % (JC / 2);
    const int  k0  = r * JC + 2 * kl;
    const int  kpg = (r * JC) / 2 + kl;
    const int  gb  = b0 + (isB ? HB : 0) + pbl;
    float cv0 = 0.0f, cv1 = 0.0f;
    uint32_t phbits = 0;     // per-mbar phase parity
    float2 xr[4];
    if (act) {
        const float* xgt = xg + (size_t)gb * xg_bs;   // t = 0
        #pragma unroll
        for (int g = 0; g < 4; ++g)
            xr[g] = *reinterpret_cast<const float2*>(xgt + g * H + k0);
    }

    // ---- P1: bf16 MMAs for one (half, slot) --------------------------------
    auto P1 = [&](int halfidx, int slot, float* gso, bool dowait) {
        const int idx = halfidx * 2 + slot;
        if (dowait) {
            uint32_t mb = sbase + idx * 8;
            mb_wait(mb, (phbits >> idx) & 1u);
            phbits ^= (1u << idx);
            if (tid == 0) mb_arrive_tx(mb, TXB);   // re-arm next phase
        }
        const uint2* hb = hl + (size_t)idx * HSLOT;
        float4 C[MPW][NT];
        #pragma unroll
        for (int mp = 0; mp < MPW; ++mp)
            #pragma unroll
            for (int nt = 0; nt < NT; ++nt) C[mp][nt] = make_float4(0.f, 0.f, 0.f, 0.f);
        #pragma unroll
        for (int kt = 0; kt < KT; ++kt) {
            int kp0 = (kh * KT + kt) * 8 + tk;
            #pragma unroll
            for (int nt = 0; nt < NT; ++nt) {
                int n = nt * 8 + gid;
                uint2 u0 = hb[n * HLS2 + kp0];
                uint2 u1 = hb[n * HLS2 + kp0 + 4];
                #pragma unroll
                for (int mp = 0; mp < MPW; ++mp) {
                    mma_bf16(C[mp][nt], Ahi[mp][kt], u0.x, u1.x);
                    mma_bf16(C[mp][nt], Ahi[mp][kt], u0.y, u1.y);
                    mma_bf16(C[mp][nt], Alo[mp][kt], u0.x, u1.x);
                }
            }
        }
        float* gout = gso + kh * (GR * SG);
        #pragma unroll
        for (int mp = 0; mp < MPW; ++mp) {
            int m0 = (mg * MPW + mp) * 16;
            #pragma unroll
            for (int nt = 0; nt < NT; ++nt) {
                int col = nt * 8 + 2 * tk;
                *reinterpret_cast<float2*>(&gout[(m0 + gid) * SG + col]) =
                    make_float2(C[mp][nt].x, C[mp][nt].y);
                *reinterpret_cast<float2*>(&gout[(m0 + gid + 8) * SG + col]) =
                    make_float2(C[mp][nt].z, C[mp][nt].w);
            }
        }
    };

    // ---- P2: gates + state + st.async broadcast + xg prefetch --------------
    auto P2 = [&](int t, int halfidx) {
        const float* gp0 = gsm + halfidx * GSM_H;
        float s0[4], s1[4];
        #pragma unroll
        for (int g = 0; g < 4; ++g) {
            float a0 = xr[g].x, a1 = xr[g].y;
            int row = (g * JC + 2 * kl) * SG + pbl;
            #pragma unroll
            for (int khx = 0; khx < KH; ++khx) {
                const float* gp = gp0 + khx * (GR * SG);
                a0 += gp[row];
                a1 += gp[row + SG];
            }
            s0[g] = a0; s1[g] = a1;
        }
        float i0 = sigf(s0[0]), i1 = sigf(s1[0]);
        float f0 = sigf(s0[1]), f1 = sigf(s1[1]);
        float g0 = tanhe(s0[2]), g1 = tanhe(s1[2]);
        float o0 = sigf(s0[3]), o1 = sigf(s1[3]);
        cv0 = f0 * cv0 + i0 * g0;
        cv1 = f1 * cv1 + i1 * g1;
        float h0v = o0 * tanhe(cv0);
        float h1v = o1 * tanhe(cv1);

        uint32_t hi2, lo2;
        split_pack(h0v, h1v, hi2, lo2);

        if (t + 1 < TT) {   // broadcast (skipped on last step)
            const int idx = halfidx * 2 + ((t + 1) & 1);
            uint32_t off_mb  = (uint32_t)idx * 8;
            uint32_t off_dat = HL_OFF +
                (uint32_t)(((idx * HB + pbl) * HLS2 + kpg) * 8);
            #pragma unroll
            for (int p = 0; p < CL; ++p)
                st_async_v2(pbase[p] + off_dat, pbase[p] + off_mb, hi2, lo2);
        }

        if (out_seq)
            out_seq[((size_t)gb * TT + t) * (H / 2) + kpg] = make_uint2(hi2, lo2);
        if (out_final && t == TT - 1)
            out_final[(size_t)gb * (H / 2) + kpg] = make_uint2(hi2, lo2);

        // prefetch xg for t+1
        int tn = (t + 1 < TT) ? t + 1 : t;
        const float* xgt = xg + (size_t)tn * xg_ts + (size_t)gb * xg_bs;
        #pragma unroll
        for (int g = 0; g < 4; ++g)
            xr[g] = *reinterpret_cast<const float2*>(xgt + g * H + k0);
    };

    // ---- prologue + main loop ----------------------------------------------
    P1(0, 0, gsm, false);          // h(0)=0, slot prefilled
    __syncthreads();

    for (int t = 0; t < TT; ++t) {
        // even bracket: P2(A,t) || P1(B, t&1)
        if (!isB && act) P2(t, 0);
        P1(1, t & 1, gsm + GSM_H, t > 0);
        __syncthreads();
        // odd bracket: P2(B,t) || P1(A, (t+1)&1)
        if (isB && act) P2(t, 1);
        if (t + 1 < TT) P1(0, (t + 1) & 1, gsm, true);
        __syncthreads();
    }
    CLUSTER_SYNC_();   // keep peer smem alive until everyone is done
}

// enc: H=256, CL=8, KH=4, MPW=2   dec: H=128, CL=4, KH=2, MPW=1  (R8 config)
__global__ void __cluster_dims__(8, 1, 1) __launch_bounds__(512, 1)
lstm_enc(const float* __restrict__ Whh, const float* __restrict__ xg,
         size_t xg_bs, int xg_ts, uint2* __restrict__ out_seq,
         uint2* __restrict__ out_final)
{
    lstm_body<DHID, 8, 4, 2>(Whh, xg, xg_bs, xg_ts, out_seq, out_final);
}
__global__ void __cluster_dims__(4, 1, 1) __launch_bounds__(512, 1)
lstm_dec(const float* __restrict__ Whh, const float* __restrict__ xg,
         size_t xg_bs, int xg_ts, uint2* __restrict__ out_seq,
         uint2* __restrict__ out_final)
{
    lstm_body<DIN, 4, 2, 1>(Whh, xg, xg_bs, xg_ts, out_seq, out_final);
}

// ---------------------------------------------------------------------------
// Elementwise pack: fp32 pairs -> {bf16 hi x2, bf16 lo x2}  (weights only)
// ---------------------------------------------------------------------------
__global__ __launch_bounds__(256) void pack_hilo_kernel(
    const float* __restrict__ src, uint2* __restrict__ dst, int npairs)
{
    int i = blockIdx.x * 256 + threadIdx.x;
    if (i >= npairs) return;
    float2 f = reinterpret_cast<const float2*>(src)[i];
    uint32_t h2, l2;
    split_pack(f.x, f.y, h2, l2);
    dst[i] = make_uint2(h2, l2);
}

// ---------------------------------------------------------------------------
// Tensor-core GEMM, BM=128 BN=128 BK=32, 512 threads, DOUBLE-BUFFERED smem
// (one __syncthreads per k-iter; global prefetch hidden under compute).
// CONVA: A is fp32, converted inline to bf16 hi/lo (exactly once per element).
// ---------------------------------------------------------------------------
template <bool CONVA>
__global__ __launch_bounds__(512, 1) void hgemm_pk(
    const void* __restrict__ Aptr,   // CONVA ? float[M][2*Kp] : uint2[M][Kp]
    const uint2* __restrict__ Bpk,   // [N][Kp]
    const float* __restrict__ b1, const float* __restrict__ b2,
    float* __restrict__ C, int M, int N, int Kp)
{
    extern __shared__ uint2 smb[];   // [2][ As(2304) + Bs(2304) ]
    constexpr int STG = 4608;

    const int tid = threadIdx.x, wid = tid >> 5, lane = tid & 31;
    const int gid = lane >> 2, tk = lane & 3;
    const int bm = blockIdx.y * 128;
    const int bn = blockIdx.x * 128;
    const int wm = (wid & 3) * 32;
    const int wn = (wid >> 2) * 32;

    float4 Cc[2][4];
    #pragma unroll
    for (int mp = 0; mp < 2; ++mp)
        #pragma unroll
        for (int nt = 0; nt < 4; ++nt) Cc[mp][nt] = make_float4(0.f, 0.f, 0.f, 0.f);

    const int row = tid >> 2;              // 0..127
    const int cq  = (tid & 3) * 4;         // uint2 col: 0,4,8,12
    const float* Ap_f  = CONVA ? (const float*)Aptr + (size_t)(bm + row) * (2 * Kp) + 2 * cq
                               : nullptr;
    const uint2* Ap_pk = CONVA ? nullptr
                               : (const uint2*)Aptr + (size_t)(bm + row) * Kp + cq;
    const uint2* Bp = Bpk + (size_t)(bn + row) * Kp + cq;

    uint2 ra[4];
    uint4 rb[2];
    auto loadA = [&](int kb) {
        if (CONVA) {
            float4 f0 = __ldg(reinterpret_cast<const float4*>(Ap_f + 2 * kb));
            float4 f1 = __ldg(reinterpret_cast<const float4*>(Ap_f + 2 * kb + 4));
            split_pack(f0.x, f0.y, ra[0].x, ra[0].y);
            split_pack(f0.z, f0.w, ra[1].x, ra[1].y);
            split_pack(f1.x, f1.y, ra[2].x, ra[2].y);
            split_pack(f1.z, f1.w, ra[3].x, ra[3].y);
        } else {
            uint4 w0 = __ldg(reinterpret_cast<const uint4*>(Ap_pk + kb));
            uint4 w1 = __ldg(reinterpret_cast<const uint4*>(Ap_pk + kb + 2));
            ra[0] = make_uint2(w0.x, w0.y); ra[1] = make_uint2(w0.z, w0.w);
            ra[2] = make_uint2(w1.x, w1.y); ra[3] = make_uint2(w1.z, w1.w);
        }
    };
    auto loadB = [&](int kb) {
        rb[0] = __ldg(reinterpret_cast<const uint4*>(Bp + kb));
        rb[1] = __ldg(reinterpret_cast<const uint4*>(Bp + kb + 2));
    };
    auto stage = [&](int s) {
        uint2* As = smb + s * STG;
        uint2* Bs = smb + s * STG + 2304;
        #pragma unroll
        for (int v = 0; v < 4; ++v) As[row * 18 + cq + v] = ra[v];
        Bs[row * 18 + cq + 0] = make_uint2(rb[0].x, rb[0].y);
        Bs[row * 18 + cq + 1] = make_uint2(rb[0].z, rb[0].w);
        Bs[row * 18 + cq + 2] = make_uint2(rb[1].x, rb[1].y);
        Bs[row * 18 + cq + 3] = make_uint2(rb[1].z, rb[1].w);
    };
    auto compute = [&](int s) {
        const uint2* As = smb + s * STG;
        const uint2* Bs = smb + s * STG + 2304;
        #pragma unroll
        for (int kt = 0; kt < 2; ++kt) {
            int kp = kt * 8 + tk;
            uint32_t Ah[2][4], Al[2][4];
            #pragma unroll
            for (int mp = 0; mp < 2; ++mp) {
                int r1 = wm + mp * 16 + gid;
                uint2 u00 = As[r1 * 18 + kp],       u01 = As[r1 * 18 + kp + 4];
                uint2 u10 = As[(r1 + 8) * 18 + kp], u11 = As[(r1 + 8) * 18 + kp + 4];
                Ah[mp][0] = u00.x; Ah[mp][1] = u10.x; Ah[mp][2] = u01.x; Ah[mp][3] = u11.x;
                Al[mp][0] = u00.y; Al[mp][1] = u10.y; Al[mp][2] = u01.y; Al[mp][3] = u11.y;
            }
            #pragma unroll
            for (int nt = 0; nt < 4; ++nt) {
                int n = wn + nt * 8 + gid;
                uint2 u0 = Bs[n * 18 + kp];
                uint2 u1 = Bs[n * 18 + kp + 4];
                #pragma unroll
                for (int mp = 0; mp < 2; ++mp) {
                    mma_bf16(Cc[mp][nt], Ah[mp], u0.x, u1.x);
                    mma_bf16(Cc[mp][nt], Ah[mp], u0.y, u1.y);
                    mma_bf16(Cc[mp][nt], Al[mp], u0.x, u1.x);
                }
            }
        }
    };

    // prologue
    loadA(0); loadB(0);
    stage(0);
    __syncthreads();

    int s = 0;
    for (int kb = 0; kb < Kp; kb += 16, s ^= 1) {
        bool more = (kb + 16 < Kp);
        if (more) { loadA(kb + 16); loadB(kb + 16); }
        compute(s);
        if (more) {
            stage(s ^ 1);
            __syncthreads();
        }
    }

    #pragma unroll
    for (int nt = 0; nt < 4; ++nt) {
        int n = bn + wn + nt * 8 + 2 * tk;
        float bb0 = b1[n]     + (b2 ? b2[n]     : 0.0f);
        float bb1 = b1[n + 1] + (b2 ? b2[n + 1] : 0.0f);
        #pragma unroll
        for (int mp = 0; mp < 2; ++mp) {
            int m1 = bm + wm + mp * 16 + gid;
            *reinterpret_cast<float2*>(C + (size_t)m1 * N + n) =
                make_float2(Cc[mp][nt].x + bb0, Cc[mp][nt].y + bb1);
            *reinterpret_cast<float2*>(C + (size_t)(m1 + 8) * N + n) =
                make_float2(Cc[mp][nt].z + bb0, Cc[mp][nt].w + bb1);
        }
    }
}

// ---------------------------------------------------------------------------
// Launch
// ---------------------------------------------------------------------------
// enc: 32 + 4*(16*132)*8 + 2*(4*128*18)*4 = 32+67584+73728 = 141344
static const int SMEM_ENC = 141344;
// dec: 32 + 4*(8*68)*8 + 2*(2*128*10)*4  = 32+17408+20480 =  37920
static const int SMEM_DEC = 37920;
// gemm: 2 stages * (2304+2304) uint2 * 8B = 73728
static const int SMEM_GEMM = 73728;

static inline int cdiv(int a, int b) { return (a + b - 1) / b; }

extern "C" void kernel_launch(void* const* d_in, const int* in_sizes, int n_in,
                              void* d_out, int out_size)
{
    (void)in_sizes; (void)n_in; (void)out_size;
    const float* x        = (const float*)d_in[0];
    const float* e0_Wih   = (const float*)d_in[1];
    const float* e0_Whh   = (const float*)d_in[2];
    const float* e0_bih   = (const float*)d_in[3];
    const float* e0_bhh   = (const float*)d_in[4];
    const float* e1_Wih   = (const float*)d_in[5];
    const float* e1_Whh   = (const float*)d_in[6];
    const float* e1_bih   = (const float*)d_in[7];
    const float* e1_bhh   = (const float*)d_in[8];
    const float* d0_Wih   = (const float*)d_in[9];
    const float* d0_Whh   = (const float*)d_in[10];
    const float* d0_bih   = (const float*)d_in[11];
    const float* d0_bhh   = (const float*)d_in[12];
    const float* d1_Wih   = (const float*)d_in[13];
    const float* d1_Whh   = (const float*)d_in[14];
    const float* d1_bih   = (const float*)d_in[15];
    const float* d1_bhh   = (const float*)d_in[16];
    const float* out_W    = (const float*)d_in[17];
    const float* out_b    = (const float*)d_in[18];
    float* out = (float*)d_out;

    float *xg, *xgd0;
    uint2 *pk, *wpk, *hTpk;
    cudaGetSymbolAddress((void**)&xg,   g_xg);
    cudaGetSymbolAddress((void**)&pk,   g_pk);
    cudaGetSymbolAddress((void**)&wpk,  g_wpk);
    cudaGetSymbolAddress((void**)&hTpk, g_hTpk);
    cudaGetSymbolAddress((void**)&xgd0, g_xgd0);

    cudaFuncSetAttribute(lstm_enc,
                         cudaFuncAttributeMaxDynamicSharedMemorySize, SMEM_ENC);
    cudaFuncSetAttribute(lstm_dec,
                         cudaFuncAttributeMaxDynamicSharedMemorySize, SMEM_DEC);
    cudaFuncSetAttribute(hgemm_pk<true>,
                         cudaFuncAttributeMaxDynamicSharedMemorySize, SMEM_GEMM);
    cudaFuncSetAttribute(hgemm_pk<false>,
                         cudaFuncAttributeMaxDynamicSharedMemorySize, SMEM_GEMM);

    const int MT = BB * TT;  // 65536

    // 1) pack e0_Wih ; xg0 = x @ e0_Wih^T + b  (x converted inline)
    {
        int nw = 4 * DHID * DIN / 2;
        pack_hilo_kernel<<<cdiv(nw, 256), 256>>>(e0_Wih, wpk, nw);
        hgemm_pk<true><<<dim3(4 * DHID / 128, MT / 128), 512, SMEM_GEMM>>>(
            x, wpk, e0_bih, e0_bhh, xg, MT, 4 * DHID, DIN / 2);
    }
    // 2) enc0 recurrence -> e0 packed
    lstm_enc<<<128, 512, SMEM_ENC>>>(
        e0_Whh, xg, (size_t)TT * 4 * DHID, 4 * DHID, pk, nullptr);

    // 3) pack e1_Wih ; xg1 = e0 @ e1_Wih^T + b
    {
        int nw = 4 * DHID * DHID / 2;
        pack_hilo_kernel<<<cdiv(nw, 256), 256>>>(e1_Wih, wpk, nw);
        hgemm_pk<false><<<dim3(4 * DHID / 128, MT / 128), 512, SMEM_GEMM>>>(
            pk, wpk, e1_bih, e1_bhh, xg, MT, 4 * DHID, DHID / 2);
    }
    // 4) enc1 recurrence -> hT packed
    lstm_enc<<<128, 512, SMEM_ENC>>>(
        e1_Whh, xg, (size_t)TT * 4 * DHID, 4 * DHID, nullptr, hTpk);

    // 5) pack d0_Wih ; xgd0 = hT @ d0_Wih^T + b
    {
        int nw = 4 * DIN * DHID / 2;
        pack_hilo_kernel<<<cdiv(nw, 256), 256>>>(d0_Wih, wpk, nw);
        hgemm_pk<false><<<dim3(4 * DIN / 128, BB / 128), 512, SMEM_GEMM>>>(
            hTpk, wpk, d0_bih, d0_bhh, xgd0, BB, 4 * DIN, DHID / 2);
    }
    // 6) dec0 recurrence (t-stride 0) -> d0 packed
    lstm_dec<<<128, 512, SMEM_DEC>>>(
        d0_Whh, xgd0, (size_t)4 * DIN, 0, pk, nullptr);

    // 7) pack d1_Wih ; xgd1 = d0 @ d1_Wih^T + b
    {
        int nw = 4 * DIN * DIN / 2;
        pack_hilo_kernel<<<cdiv(nw, 256), 256>>>(d1_Wih, wpk, nw);
        hgemm_pk<false><<<dim3(4 * DIN / 128, MT / 128), 512, SMEM_GEMM>>>(
            pk, wpk, d1_bih, d1_bhh, xg, MT, 4 * DIN, DIN / 2);
    }
    // 8) dec1 recurrence -> d1 packed
    lstm_dec<<<128, 512, SMEM_DEC>>>(
        d1_Whh, xg, (size_t)TT * 4 * DIN, 4 * DIN, pk, nullptr);

    // 9) pack out_W ; out = d1 @ out_W^T + out_b
    {
        int nw = DIN * DIN / 2;
        pack_hilo_kernel<<<cdiv(nw, 256), 256>>>(out_W, wpk, nw);
        hgemm_pk<false><<<dim3(DIN / 128, MT / 128), 512, SMEM_GEMM>>>(
            pk, wpk, out_b, nullptr, out, MT, DIN, DIN / 2);
    }
}